// round 5
// baseline (speedup 1.0000x reference)
#include <cuda_runtime.h>
#include <math.h>

#define NGRAPH 512
#define NPG    512      // nodes per graph
#define EPG    8192     // edges per graph
#define CIN    128
#define HID    32
#define PAD    33       // padded row stride for 32-ch activation buffers
#define KTOP   20

// monotonic float -> uint mapping (order-preserving)
__device__ __forceinline__ unsigned ordkey(float f) {
    unsigned u = __float_as_uint(f);
    return (u & 0x80000000u) ? ~u : (u | 0x80000000u);
}

// Accurate tanh that survives --use_fast_math (tanhf would lower to the
// HW tanh.approx with ~6e-4 abs error; this stays ~1e-6).
__device__ __forceinline__ float tanh_acc(float x) {
    float ax = fabsf(x);
    float e  = __expf(ax + ax);                    // exp(2|x|), ~2 ulp
    float r  = 1.0f - __fdividef(2.0f, e + 1.0f);  // inf -> 0 -> r=1 (saturate)
    return copysignf(r, x);
}

__global__ __launch_bounds__(512, 1)
void dgcnn_fused_kernel(const float* __restrict__ x,
                        const int*   __restrict__ esrc,
                        const int*   __restrict__ edst,
                        const float* __restrict__ W0g, const float* __restrict__ b0g,
                        const float* __restrict__ W1g, const float* __restrict__ b1g,
                        const float* __restrict__ W2g, const float* __restrict__ b2g,
                        const float* __restrict__ c1wg, const float* __restrict__ c1bg,
                        const float* __restrict__ c2wg, const float* __restrict__ c2bg,
                        const float* __restrict__ l1wg, const float* __restrict__ l1bg,
                        const float* __restrict__ l2wg, const float* __restrict__ l2bg,
                        float* __restrict__ out)
{
    extern __shared__ char smem[];
    float* A   = (float*)smem;                    // 512*33 floats  (h buffer)
    float* B   = A + NPG * PAD;                   // 512*33 floats  (x1)
    float* CX  = B + NPG * PAD;                   // 16416 floats   (x stage / x2)
    float* dis = CX + 16416;                      // 512 floats
    int*   indptr = (int*)(dis + NPG);            // 514 ints
    unsigned short* csr = (unsigned short*)(indptr + 514);   // 8192 u16
    float* x3v = (float*)(csr + EPG);             // 512 floats
    // +2 floats of padding so U is 16-byte aligned (float4 loads from it)
    char*  U   = (char*)(x3v + NPG + 2);          // 4096 B union scratch, 16B-aligned

    const int tid  = threadIdx.x;
    const int lane = tid & 31;
    const int wid  = tid >> 5;          // 0..15
    const int g    = blockIdx.x;
    const int nbase = g * NPG;
    const long ebase = (long)g * EPG;

    // ================= degree count =================
    indptr[tid] = 0;
    if (tid < 2) indptr[512 + tid] = 0;   // tail entries (block has only 512 threads)
    __syncthreads();

    #pragma unroll
    for (int i = 0; i < EPG / 512; i++) {
        int e = tid + i * 512;
        int d = edst[ebase + e] - nbase;
        atomicAdd(&indptr[d + 1], 1);
    }
    __syncthreads();

    // dis = rsqrt(deg + 1)  (self loop)
    {
        int cnt = indptr[tid + 1];
        dis[tid] = rsqrtf((float)cnt + 1.0f);
    }

    // ================= exclusive scan -> indptr =================
    {
        int v = indptr[tid + 1];
        #pragma unroll
        for (int off = 1; off < 32; off <<= 1) {
            int n = __shfl_up_sync(0xffffffffu, v, off);
            if (lane >= off) v += n;
        }
        int* wsum = (int*)U;
        if (lane == 31) wsum[wid] = v;
        __syncthreads();
        if (wid == 0) {
            int s = (lane < 16) ? wsum[lane] : 0;
            #pragma unroll
            for (int off = 1; off < 16; off <<= 1) {
                int n = __shfl_up_sync(0xffffffffu, s, off);
                if (lane >= off) s += n;
            }
            if (lane < 16) wsum[lane] = s;
        }
        __syncthreads();
        int prefix = (wid > 0) ? wsum[wid - 1] : 0;
        int incl = v + prefix;
        __syncthreads();            // everyone done reading wsum
        indptr[tid + 1] = incl;
        if (tid == 0) indptr[0] = 0;
        __syncthreads();
    }

    // ================= CSR fill =================
    {
        int* pos = (int*)U;
        pos[tid] = indptr[tid];
        __syncthreads();
        #pragma unroll
        for (int i = 0; i < EPG / 512; i++) {
            int e = tid + i * 512;
            int s = esrc[ebase + e] - nbase;
            int d = edst[ebase + e] - nbase;
            int p = atomicAdd(&pos[d], 1);
            csr[p] = (unsigned short)s;
        }
    }
    // sync happens at top of L1 loop

    // ================= Layer 1 matmul: h0 = x_g @ W0 -> A =================
    {
        float acc[32];
        #pragma unroll
        for (int o = 0; o < 32; o++) acc[o] = 0.f;
        float* Wc = (float*)U;
        const float* xg = x + (size_t)nbase * CIN;
        for (int cb = 0; cb < 4; cb++) {
            __syncthreads();
            // stage x chunk TRANSPOSED: CX[c*513 + n], coalesced global reads
            #pragma unroll
            for (int i = 0; i < 32; i++) {
                int n = i * 16 + wid;
                CX[lane * 513 + n] = xg[(size_t)n * CIN + cb * 32 + lane];
            }
            // stage W0 chunk (32x32)
            Wc[tid]       = W0g[cb * 1024 + tid];
            Wc[tid + 512] = W0g[cb * 1024 + tid + 512];
            __syncthreads();
            const float4* W4 = (const float4*)Wc;
            #pragma unroll 4
            for (int c = 0; c < 32; c++) {
                float xv = CX[c * 513 + tid];
                #pragma unroll
                for (int o4 = 0; o4 < 8; o4++) {
                    float4 wv = W4[c * 8 + o4];
                    acc[o4*4+0] = fmaf(xv, wv.x, acc[o4*4+0]);
                    acc[o4*4+1] = fmaf(xv, wv.y, acc[o4*4+1]);
                    acc[o4*4+2] = fmaf(xv, wv.z, acc[o4*4+2]);
                    acc[o4*4+3] = fmaf(xv, wv.w, acc[o4*4+3]);
                }
            }
        }
        #pragma unroll
        for (int o = 0; o < 32; o++) A[tid * PAD + o] = acc[o];
    }
    __syncthreads();

    // ================= Layer 1 gather: x1 = tanh(D^-.5 (A+I) D^-.5 h0 + b0) -> B =================
    {
        float bl = b0g[lane];
        for (int n = wid; n < NPG; n += 16) {
            float dn = dis[n];
            float acc = A[n * PAD + lane] * dn;     // self-loop folded into sum
            int e = indptr[n], end = indptr[n + 1];
            for (; e + 1 < end; e += 2) {
                int s0 = csr[e], s1 = csr[e + 1];
                acc = fmaf(A[s0 * PAD + lane], dis[s0], acc);
                acc = fmaf(A[s1 * PAD + lane], dis[s1], acc);
            }
            if (e < end) {
                int s0 = csr[e];
                acc = fmaf(A[s0 * PAD + lane], dis[s0], acc);
            }
            B[n * PAD + lane] = tanh_acc(fmaf(acc, dn, bl));
        }
    }
    __syncthreads();

    // ================= Layer 2 matmul: h1 = x1 @ W1 -> A =================
    {
        float* Wc = (float*)U;
        Wc[tid]       = W1g[tid];
        Wc[tid + 512] = W1g[tid + 512];
        __syncthreads();
        float acc[32];
        #pragma unroll
        for (int o = 0; o < 32; o++) acc[o] = 0.f;
        const float4* W4 = (const float4*)Wc;
        #pragma unroll 4
        for (int c = 0; c < 32; c++) {
            float xv = B[tid * PAD + c];
            #pragma unroll
            for (int o4 = 0; o4 < 8; o4++) {
                float4 wv = W4[c * 8 + o4];
                acc[o4*4+0] = fmaf(xv, wv.x, acc[o4*4+0]);
                acc[o4*4+1] = fmaf(xv, wv.y, acc[o4*4+1]);
                acc[o4*4+2] = fmaf(xv, wv.z, acc[o4*4+2]);
                acc[o4*4+3] = fmaf(xv, wv.w, acc[o4*4+3]);
            }
        }
        #pragma unroll
        for (int o = 0; o < 32; o++) A[tid * PAD + o] = acc[o];
    }
    __syncthreads();

    // ================= Layer 2 gather -> x2 in CX (unpadded 512x32) =================
    {
        float bl = b1g[lane];
        for (int n = wid; n < NPG; n += 16) {
            float dn = dis[n];
            float acc = A[n * PAD + lane] * dn;
            int e = indptr[n], end = indptr[n + 1];
            for (; e + 1 < end; e += 2) {
                int s0 = csr[e], s1 = csr[e + 1];
                acc = fmaf(A[s0 * PAD + lane], dis[s0], acc);
                acc = fmaf(A[s1 * PAD + lane], dis[s1], acc);
            }
            if (e < end) {
                int s0 = csr[e];
                acc = fmaf(A[s0 * PAD + lane], dis[s0], acc);
            }
            CX[n * 32 + lane] = tanh_acc(fmaf(acc, dn, bl));
        }
    }
    __syncthreads();

    // ================= Layer 3: h2 = x2 @ W2 (scalar/node), then gather -> x3v =================
    {
        float w2l = W2g[lane];
        float* h2 = (float*)U;
        for (int n = wid; n < NPG; n += 16) {
            float v = CX[n * 32 + lane] * w2l;
            #pragma unroll
            for (int off = 16; off; off >>= 1) v += __shfl_down_sync(0xffffffffu, v, off);
            if (lane == 0) h2[n] = v;
        }
    }
    __syncthreads();
    {
        float* h2 = (float*)U;
        float b2 = b2g[0];
        for (int n = wid; n < NPG; n += 16) {
            int beg = indptr[n], end = indptr[n + 1];
            float p = 0.f;
            for (int e = beg + lane; e < end; e += 32) {
                int s = csr[e];
                p = fmaf(h2[s], dis[s], p);
            }
            #pragma unroll
            for (int off = 16; off; off >>= 1) p += __shfl_down_sync(0xffffffffu, p, off);
            if (lane == 0) {
                float dn = dis[n];
                float tot = p + h2[n] * dn;
                x3v[n] = tanh_acc(fmaf(tot, dn, b2));
            }
        }
    }
    __syncthreads();

    // ================= stable top-K: bitonic sort of 512 keys (desc value, asc idx) =================
    unsigned long long* keys = (unsigned long long*)U;
    keys[tid] = ((unsigned long long)ordkey(x3v[tid]) << 32)
              | (unsigned long long)(0xFFFFFFFFu - (unsigned)tid);
    __syncthreads();
    for (int k = 2; k <= 512; k <<= 1) {
        for (int j = k >> 1; j > 0; j >>= 1) {
            int ixj = tid ^ j;
            if (ixj > tid) {
                unsigned long long a = keys[tid], b = keys[ixj];
                bool desc = ((tid & k) == 0);
                if (desc ? (a < b) : (a > b)) { keys[tid] = b; keys[ixj] = a; }
            }
            __syncthreads();
        }
    }

    // ================= tail: conv1 -> maxpool -> conv2 -> lin1 -> lin2 =================
    float* hconv = A;             // 320
    float* hp    = A + 320;       // 160
    float* feat2 = A + 480;       // 192
    float* o1    = A + 672;       // 128
    int*   topn  = (int*)(A + 800);   // 20
    float* WS  = (float*)csr;     // CSR dead; 16 KB scratch for small weights
    float* c1w = WS;              // 1040
    float* c1b = WS + 1040;       // 16
    float* c2w = WS + 1056;       // 2560
    float* c2b = WS + 3616;       // 32

    for (int i = tid; i < 1040; i += 512) c1w[i] = c1wg[i];
    if (tid < 16) c1b[tid] = c1bg[tid];
    for (int i = tid; i < 2560; i += 512) c2w[i] = c2wg[i];
    if (tid < 32) c2b[tid] = c2bg[tid];
    if (tid < KTOP) topn[tid] = (int)(0xFFFFFFFFu - (unsigned)(keys[tid] & 0xFFFFFFFFull));
    __syncthreads();

    // conv1: [G,16,K] = relu(pooled . w + b), pooled[k] = [x1|x2|x3](topn[k])
    if (tid < 16 * KTOP) {
        int o = tid & 15, k = tid >> 4;
        int n = topn[k];
        float acc = c1b[o];
        const float* wrow = c1w + o * 65;
        #pragma unroll
        for (int c = 0; c < 32; c++) acc = fmaf(B[n * PAD + c], wrow[c], acc);
        #pragma unroll
        for (int c = 0; c < 32; c++) acc = fmaf(CX[n * 32 + c], wrow[32 + c], acc);
        acc = fmaf(x3v[n], wrow[64], acc);
        hconv[o * KTOP + k] = fmaxf(acc, 0.f);
    }
    __syncthreads();

    // maxpool(2,2): [16,20] -> [16,10]
    if (tid < 160) {
        int o = tid / 10, t = tid % 10;
        hp[o * 10 + t] = fmaxf(hconv[o * KTOP + 2 * t], hconv[o * KTOP + 2 * t + 1]);
    }
    __syncthreads();

    // conv2: Conv1d(16,32,5) valid -> [32,6], relu; flatten o*6+t
    if (tid < 192) {
        int o = tid / 6, t = tid % 6;
        float acc = c2b[o];
        #pragma unroll
        for (int i2 = 0; i2 < 16; i2++)
            #pragma unroll
            for (int j = 0; j < 5; j++)
                acc = fmaf(hp[i2 * 10 + t + j], c2w[(o * 16 + i2) * 5 + j], acc);
        feat2[o * 6 + t] = fmaxf(acc, 0.f);
    }
    __syncthreads();

    // lin1: [192] @ [192,128] + b, relu
    if (tid < 128) {
        float acc = l1bg[tid];
        #pragma unroll 8
        for (int c = 0; c < 192; c++)
            acc = fmaf(feat2[c], l1wg[c * 128 + tid], acc);
        o1[tid] = fmaxf(acc, 0.f);
    }
    __syncthreads();

    // lin2: [128] @ [128,2] + b -> out[g,0..1]
    if (tid < 64) {
        int w = tid >> 5, l = tid & 31;
        float p = o1[l]        * l2wg[l * 2 + w]
                + o1[l + 32]   * l2wg[(l + 32) * 2 + w]
                + o1[l + 64]   * l2wg[(l + 64) * 2 + w]
                + o1[l + 96]   * l2wg[(l + 96) * 2 + w];
        #pragma unroll
        for (int off = 16; off; off >>= 1) p += __shfl_down_sync(0xffffffffu, p, off);
        if (l == 0) out[g * 2 + w] = p + l2bg[w];
    }
}

extern "C" void kernel_launch(void* const* d_in, const int* in_sizes, int n_in,
                              void* d_out, int out_size)
{
    const float* x    = (const float*)d_in[0];
    const int*   ei   = (const int*)d_in[1];
    // d_in[2] = batch (unused; graphs are contiguous)
    const float* W0   = (const float*)d_in[3];
    const float* b0   = (const float*)d_in[4];
    const float* W1   = (const float*)d_in[5];
    const float* b1   = (const float*)d_in[6];
    const float* W2   = (const float*)d_in[7];
    const float* b2   = (const float*)d_in[8];
    const float* c1w  = (const float*)d_in[9];
    const float* c1b  = (const float*)d_in[10];
    const float* c2w  = (const float*)d_in[11];
    const float* c2b  = (const float*)d_in[12];
    const float* l1w  = (const float*)d_in[13];
    const float* l1b  = (const float*)d_in[14];
    const float* l2w  = (const float*)d_in[15];
    const float* l2b  = (const float*)d_in[16];
    float* out = (float*)d_out;

    const long E = (long)in_sizes[1] / 2;   // 4,194,304
    const int* esrc = ei;
    const int* edst = ei + E;

    // dynamic smem: A,B (512*33) + CX (16416) + dis (512) floats,
    // indptr 514 ints, csr 8192 u16, x3v (512+2 pad) floats, U 4096 B
    const size_t SMEM = (size_t)(512 * 33 * 2 + 16416 + 512) * 4
                      + 514 * 4 + EPG * 2 + (512 + 2) * 4 + 4096;
    cudaFuncSetAttribute(dgcnn_fused_kernel,
                         cudaFuncAttributeMaxDynamicSharedMemorySize, (int)SMEM);

    dgcnn_fused_kernel<<<NGRAPH, 512, SMEM>>>(
        x, esrc, edst, W0, b0, W1, b1, W2, b2,
        c1w, c1b, c2w, c2b, l1w, l1b, l2w, l2b, out);
}

// round 8
// speedup vs baseline: 1.0111x; 1.0111x over previous
#include <cuda_runtime.h>
#include <math.h>

#define NGRAPH 512
#define NPG    512      // nodes per graph
#define EPG    8192     // edges per graph
#define CIN    128
#define HID    32
#define PAD    33       // padded row stride for 32-ch activation buffers
#define KTOP   20

// monotonic float -> uint mapping (order-preserving)
__device__ __forceinline__ unsigned ordkey(float f) {
    unsigned u = __float_as_uint(f);
    return (u & 0x80000000u) ? ~u : (u | 0x80000000u);
}

// Accurate tanh that survives --use_fast_math (tanhf would lower to the
// HW tanh.approx with ~6e-4 abs error; this stays ~1e-6).
__device__ __forceinline__ float tanh_acc(float x) {
    float ax = fabsf(x);
    float e  = __expf(ax + ax);                    // exp(2|x|), ~2 ulp
    float r  = 1.0f - __fdividef(2.0f, e + 1.0f);  // inf -> 0 -> r=1 (saturate)
    return copysignf(r, x);
}

// packed f32x2 fma: d = a*b + d  (Blackwell FFMA2; halves FFMA issue count)
#define FFMA2(d, a, b) asm("fma.rn.f32x2 %0, %1, %2, %0;" : "+l"(d) : "l"(a), "l"(b))
// pack (v, v) into one 64-bit f32x2 operand
__device__ __forceinline__ unsigned long long packdup(float v) {
    unsigned long long r;
    asm("mov.b64 %0, {%1, %1};" : "=l"(r) : "r"(__float_as_uint(v)));
    return r;
}

__global__ __launch_bounds__(512, 1)
void dgcnn_fused_kernel(const float* __restrict__ x,
                        const int*   __restrict__ esrc,
                        const int*   __restrict__ edst,
                        const float* __restrict__ W0g, const float* __restrict__ b0g,
                        const float* __restrict__ W1g, const float* __restrict__ b1g,
                        const float* __restrict__ W2g, const float* __restrict__ b2g,
                        const float* __restrict__ c1wg, const float* __restrict__ c1bg,
                        const float* __restrict__ c2wg, const float* __restrict__ c2bg,
                        const float* __restrict__ l1wg, const float* __restrict__ l1bg,
                        const float* __restrict__ l2wg, const float* __restrict__ l2bg,
                        float* __restrict__ out)
{
    extern __shared__ char smem[];
    float* A   = (float*)smem;                    // 512*33 floats  (h buffer, pre-scaled by dis)
    float* B   = A + NPG * PAD;                   // 512*33 floats  (x1)
    float* CX  = B + NPG * PAD;                   // 16416 floats   (x stage / x2)
    float* dis = CX + 16416;                      // 512 floats
    int*   indptr = (int*)(dis + NPG);            // 514 ints
    unsigned short* csr = (unsigned short*)(indptr + 514);   // 8192 u16 (4B-aligned base)
    float* x3v = (float*)(csr + EPG);             // 512 floats
    // +2 floats of padding so U is 16-byte aligned (float4/ulonglong2 loads from it)
    char*  U   = (char*)(x3v + NPG + 2);          // 4096 B union scratch, 16B-aligned

    const int tid  = threadIdx.x;
    const int lane = tid & 31;
    const int wid  = tid >> 5;          // 0..15
    const int g    = blockIdx.x;
    const int nbase = g * NPG;
    const long ebase = (long)g * EPG;

    // ================= degree count =================
    indptr[tid] = 0;
    if (tid < 2) indptr[512 + tid] = 0;   // tail entries (block has only 512 threads)
    __syncthreads();

    #pragma unroll
    for (int i = 0; i < EPG / 512; i++) {
        int e = tid + i * 512;
        int d = edst[ebase + e] - nbase;
        atomicAdd(&indptr[d + 1], 1);
    }
    __syncthreads();

    // dis = rsqrt(deg + 1)  (self loop)
    {
        int cnt = indptr[tid + 1];
        dis[tid] = rsqrtf((float)cnt + 1.0f);
    }

    // ================= exclusive scan -> indptr =================
    {
        int v = indptr[tid + 1];
        #pragma unroll
        for (int off = 1; off < 32; off <<= 1) {
            int n = __shfl_up_sync(0xffffffffu, v, off);
            if (lane >= off) v += n;
        }
        int* wsum = (int*)U;
        if (lane == 31) wsum[wid] = v;
        __syncthreads();
        if (wid == 0) {
            int s = (lane < 16) ? wsum[lane] : 0;
            #pragma unroll
            for (int off = 1; off < 16; off <<= 1) {
                int n = __shfl_up_sync(0xffffffffu, s, off);
                if (lane >= off) s += n;
            }
            if (lane < 16) wsum[lane] = s;
        }
        __syncthreads();
        int prefix = (wid > 0) ? wsum[wid - 1] : 0;
        int incl = v + prefix;
        __syncthreads();            // everyone done reading wsum
        indptr[tid + 1] = incl;
        if (tid == 0) indptr[0] = 0;
        __syncthreads();
    }

    // ================= CSR fill =================
    {
        int* pos = (int*)U;
        pos[tid] = indptr[tid];
        __syncthreads();
        #pragma unroll
        for (int i = 0; i < EPG / 512; i++) {
            int e = tid + i * 512;
            int s = esrc[ebase + e] - nbase;
            int d = edst[ebase + e] - nbase;
            int p = atomicAdd(&pos[d], 1);
            csr[p] = (unsigned short)s;
        }
    }
    // sync happens at top of L1 loop

    // ================= Layer 1 matmul: A = (x_g @ W0) * dis  (pre-scaled) =================
    {
        unsigned long long acc2[16];
        #pragma unroll
        for (int j = 0; j < 16; j++) acc2[j] = 0ull;
        float* Wc = (float*)U;
        const float* xg = x + (size_t)nbase * CIN;
        for (int cb = 0; cb < 4; cb++) {
            __syncthreads();
            // stage x chunk TRANSPOSED: CX[c*513 + n], coalesced global reads
            #pragma unroll
            for (int i = 0; i < 32; i++) {
                int n = i * 16 + wid;
                CX[lane * 513 + n] = xg[(size_t)n * CIN + cb * 32 + lane];
            }
            // stage W0 chunk (32x32)
            Wc[tid]       = W0g[cb * 1024 + tid];
            Wc[tid + 512] = W0g[cb * 1024 + tid + 512];
            __syncthreads();
            const ulonglong2* W2p = (const ulonglong2*)Wc;
            #pragma unroll 4
            for (int c = 0; c < 32; c++) {
                unsigned long long xx = packdup(CX[c * 513 + tid]);
                #pragma unroll
                for (int o4 = 0; o4 < 8; o4++) {
                    ulonglong2 wv = W2p[c * 8 + o4];
                    FFMA2(acc2[o4 * 2 + 0], xx, wv.x);
                    FFMA2(acc2[o4 * 2 + 1], xx, wv.y);
                }
            }
        }
        float dn = dis[tid];
        #pragma unroll
        for (int o4 = 0; o4 < 8; o4++) {
            float2 f0 = *reinterpret_cast<float2*>(&acc2[o4 * 2 + 0]);
            float2 f1 = *reinterpret_cast<float2*>(&acc2[o4 * 2 + 1]);
            A[tid * PAD + o4 * 4 + 0] = f0.x * dn;
            A[tid * PAD + o4 * 4 + 1] = f0.y * dn;
            A[tid * PAD + o4 * 4 + 2] = f1.x * dn;
            A[tid * PAD + o4 * 4 + 3] = f1.y * dn;
        }
    }
    __syncthreads();

    // ================= Layer 1 gather: x1 = tanh((self + sum A'[s]) * dn + b0) -> B =================
    {
        float bl = b0g[lane];
        for (int n = wid; n < NPG; n += 16) {
            float acc0 = A[n * PAD + lane];     // self term (A pre-scaled by dis)
            float acc1 = 0.f;
            int e = indptr[n], end = indptr[n + 1];
            if (e < end && (e & 1)) {           // align e for u32 pair reads
                acc1 = A[csr[e] * PAD + lane];
                e++;
            }
            for (; e + 3 < end; e += 4) {
                unsigned v0 = *(const unsigned*)(csr + e);
                unsigned v1 = *(const unsigned*)(csr + e + 2);
                acc0 += A[(v0 & 0xffffu) * PAD + lane];
                acc1 += A[(v0 >> 16)     * PAD + lane];
                acc0 += A[(v1 & 0xffffu) * PAD + lane];
                acc1 += A[(v1 >> 16)     * PAD + lane];
            }
            for (; e < end; e++)
                acc0 += A[csr[e] * PAD + lane];
            B[n * PAD + lane] = tanh_acc(fmaf(acc0 + acc1, dis[n], bl));
        }
    }
    __syncthreads();

    // ================= Layer 2 matmul: A = (x1 @ W1) * dis  (pre-scaled) =================
    {
        float* Wc = (float*)U;
        Wc[tid]       = W1g[tid];
        Wc[tid + 512] = W1g[tid + 512];
        __syncthreads();
        unsigned long long acc2[16];
        #pragma unroll
        for (int j = 0; j < 16; j++) acc2[j] = 0ull;
        const ulonglong2* W2p = (const ulonglong2*)Wc;
        #pragma unroll 4
        for (int c = 0; c < 32; c++) {
            unsigned long long xx = packdup(B[tid * PAD + c]);
            #pragma unroll
            for (int o4 = 0; o4 < 8; o4++) {
                ulonglong2 wv = W2p[c * 8 + o4];
                FFMA2(acc2[o4 * 2 + 0], xx, wv.x);
                FFMA2(acc2[o4 * 2 + 1], xx, wv.y);
            }
        }
        float dn = dis[tid];
        #pragma unroll
        for (int o4 = 0; o4 < 8; o4++) {
            float2 f0 = *reinterpret_cast<float2*>(&acc2[o4 * 2 + 0]);
            float2 f1 = *reinterpret_cast<float2*>(&acc2[o4 * 2 + 1]);
            A[tid * PAD + o4 * 4 + 0] = f0.x * dn;
            A[tid * PAD + o4 * 4 + 1] = f0.y * dn;
            A[tid * PAD + o4 * 4 + 2] = f1.x * dn;
            A[tid * PAD + o4 * 4 + 3] = f1.y * dn;
        }
    }
    __syncthreads();

    // ================= Layer 2 gather -> x2 in CX (unpadded 512x32) =================
    {
        float bl = b1g[lane];
        for (int n = wid; n < NPG; n += 16) {
            float acc0 = A[n * PAD + lane];     // self term (pre-scaled)
            float acc1 = 0.f;
            int e = indptr[n], end = indptr[n + 1];
            if (e < end && (e & 1)) {
                acc1 = A[csr[e] * PAD + lane];
                e++;
            }
            for (; e + 3 < end; e += 4) {
                unsigned v0 = *(const unsigned*)(csr + e);
                unsigned v1 = *(const unsigned*)(csr + e + 2);
                acc0 += A[(v0 & 0xffffu) * PAD + lane];
                acc1 += A[(v0 >> 16)     * PAD + lane];
                acc0 += A[(v1 & 0xffffu) * PAD + lane];
                acc1 += A[(v1 >> 16)     * PAD + lane];
            }
            for (; e < end; e++)
                acc0 += A[csr[e] * PAD + lane];
            CX[n * 32 + lane] = tanh_acc(fmaf(acc0 + acc1, dis[n], bl));
        }
    }
    __syncthreads();

    // ================= Layer 3: h2' = (x2 @ W2)*dis, then gather -> x3v =================
    {
        float w2l = W2g[lane];
        float* h2 = (float*)U;
        for (int n = wid; n < NPG; n += 16) {
            float v = CX[n * 32 + lane] * w2l;
            #pragma unroll
            for (int off = 16; off; off >>= 1) v += __shfl_down_sync(0xffffffffu, v, off);
            if (lane == 0) h2[n] = v * dis[n];   // pre-scaled
        }
    }
    __syncthreads();
    {
        float* h2 = (float*)U;
        float b2 = b2g[0];
        for (int n = wid; n < NPG; n += 16) {
            int beg = indptr[n], end = indptr[n + 1];
            float p = 0.f;
            for (int e = beg + lane; e < end; e += 32)
                p += h2[csr[e]];
            #pragma unroll
            for (int off = 16; off; off >>= 1) p += __shfl_down_sync(0xffffffffu, p, off);
            if (lane == 0) {
                float tot = p + h2[n];
                x3v[n] = tanh_acc(fmaf(tot, dis[n], b2));
            }
        }
    }
    __syncthreads();

    // ================= stable top-K: bitonic sort of 512 keys (desc value, asc idx) =================
    unsigned long long* keys = (unsigned long long*)U;
    keys[tid] = ((unsigned long long)ordkey(x3v[tid]) << 32)
              | (unsigned long long)(0xFFFFFFFFu - (unsigned)tid);
    __syncthreads();
    for (int k = 2; k <= 512; k <<= 1) {
        for (int j = k >> 1; j > 0; j >>= 1) {
            int ixj = tid ^ j;
            if (ixj > tid) {
                unsigned long long a = keys[tid], b = keys[ixj];
                bool desc = ((tid & k) == 0);
                if (desc ? (a < b) : (a > b)) { keys[tid] = b; keys[ixj] = a; }
            }
            __syncthreads();
        }
    }

    // ================= tail: conv1 -> maxpool -> conv2 -> lin1 -> lin2 =================
    float* hconv = A;             // 320
    float* hp    = A + 320;       // 160
    float* feat2 = A + 480;       // 192
    float* o1    = A + 672;       // 128
    int*   topn  = (int*)(A + 800);   // 20
    float* WS  = (float*)csr;     // CSR dead; 16 KB scratch for small weights
    float* c1w = WS;              // 1040
    float* c1b = WS + 1040;       // 16
    float* c2w = WS + 1056;       // 2560
    float* c2b = WS + 3616;       // 32

    for (int i = tid; i < 1040; i += 512) c1w[i] = c1wg[i];
    if (tid < 16) c1b[tid] = c1bg[tid];
    for (int i = tid; i < 2560; i += 512) c2w[i] = c2wg[i];
    if (tid < 32) c2b[tid] = c2bg[tid];
    if (tid < KTOP) topn[tid] = (int)(0xFFFFFFFFu - (unsigned)(keys[tid] & 0xFFFFFFFFull));
    __syncthreads();

    // conv1: [G,16,K] = relu(pooled . w + b), pooled[k] = [x1|x2|x3](topn[k])
    if (tid < 16 * KTOP) {
        int o = tid & 15, k = tid >> 4;
        int n = topn[k];
        float acc = c1b[o];
        const float* wrow = c1w + o * 65;
        #pragma unroll
        for (int c = 0; c < 32; c++) acc = fmaf(B[n * PAD + c], wrow[c], acc);
        #pragma unroll
        for (int c = 0; c < 32; c++) acc = fmaf(CX[n * 32 + c], wrow[32 + c], acc);
        acc = fmaf(x3v[n], wrow[64], acc);
        hconv[o * KTOP + k] = fmaxf(acc, 0.f);
    }
    __syncthreads();

    // maxpool(2,2): [16,20] -> [16,10]
    if (tid < 160) {
        int o = tid / 10, t = tid % 10;
        hp[o * 10 + t] = fmaxf(hconv[o * KTOP + 2 * t], hconv[o * KTOP + 2 * t + 1]);
    }
    __syncthreads();

    // conv2: Conv1d(16,32,5) valid -> [32,6], relu; flatten o*6+t
    if (tid < 192) {
        int o = tid / 6, t = tid % 6;
        float acc = c2b[o];
        #pragma unroll
        for (int i2 = 0; i2 < 16; i2++)
            #pragma unroll
            for (int j = 0; j < 5; j++)
                acc = fmaf(hp[i2 * 10 + t + j], c2w[(o * 16 + i2) * 5 + j], acc);
        feat2[o * 6 + t] = fmaxf(acc, 0.f);
    }
    __syncthreads();

    // lin1: [192] @ [192,128] + b, relu
    if (tid < 128) {
        float acc = l1bg[tid];
        #pragma unroll 8
        for (int c = 0; c < 192; c++)
            acc = fmaf(feat2[c], l1wg[c * 128 + tid], acc);
        o1[tid] = fmaxf(acc, 0.f);
    }
    __syncthreads();

    // lin2: [128] @ [128,2] + b -> out[g,0..1]
    if (tid < 64) {
        int w = tid >> 5, l = tid & 31;
        float p = o1[l]        * l2wg[l * 2 + w]
                + o1[l + 32]   * l2wg[(l + 32) * 2 + w]
                + o1[l + 64]   * l2wg[(l + 64) * 2 + w]
                + o1[l + 96]   * l2wg[(l + 96) * 2 + w];
        #pragma unroll
        for (int off = 16; off; off >>= 1) p += __shfl_down_sync(0xffffffffu, p, off);
        if (l == 0) out[g * 2 + w] = p + l2bg[w];
    }
}

extern "C" void kernel_launch(void* const* d_in, const int* in_sizes, int n_in,
                              void* d_out, int out_size)
{
    const float* x    = (const float*)d_in[0];
    const int*   ei   = (const int*)d_in[1];
    // d_in[2] = batch (unused; graphs are contiguous)
    const float* W0   = (const float*)d_in[3];
    const float* b0   = (const float*)d_in[4];
    const float* W1   = (const float*)d_in[5];
    const float* b1   = (const float*)d_in[6];
    const float* W2   = (const float*)d_in[7];
    const float* b2   = (const float*)d_in[8];
    const float* c1w  = (const float*)d_in[9];
    const float* c1b  = (const float*)d_in[10];
    const float* c2w  = (const float*)d_in[11];
    const float* c2b  = (const float*)d_in[12];
    const float* l1w  = (const float*)d_in[13];
    const float* l1b  = (const float*)d_in[14];
    const float* l2w  = (const float*)d_in[15];
    const float* l2b  = (const float*)d_in[16];
    float* out = (float*)d_out;

    const long E = (long)in_sizes[1] / 2;   // 4,194,304
    const int* esrc = ei;
    const int* edst = ei + E;

    // dynamic smem: A,B (512*33) + CX (16416) + dis (512) floats,
    // indptr 514 ints, csr 8192 u16, x3v (512+2 pad) floats, U 4096 B
    const size_t SMEM = (size_t)(512 * 33 * 2 + 16416 + 512) * 4
                      + 514 * 4 + EPG * 2 + (512 + 2) * 4 + 4096;
    cudaFuncSetAttribute(dgcnn_fused_kernel,
                         cudaFuncAttributeMaxDynamicSharedMemorySize, (int)SMEM);

    dgcnn_fused_kernel<<<NGRAPH, 512, SMEM>>>(
        x, esrc, edst, W0, b0, W1, b1, W2, b2,
        c1w, c1b, c2w, c2b, l1w, l1b, l2w, l2b, out);
}

// round 10
// speedup vs baseline: 1.0381x; 1.0268x over previous
#include <cuda_runtime.h>
#include <math.h>

#define NGRAPH 512
#define NPG    512      // nodes per graph
#define EPG    8192     // edges per graph
#define CIN    128
#define HID    32
#define KTOP   20

// monotonic float -> uint mapping (order-preserving)
__device__ __forceinline__ unsigned ordkey(float f) {
    unsigned u = __float_as_uint(f);
    return (u & 0x80000000u) ? ~u : (u | 0x80000000u);
}

// Accurate tanh that survives --use_fast_math (tanhf would lower to the
// HW tanh.approx with ~6e-4 abs error; this stays ~1e-6).
__device__ __forceinline__ float tanh_acc(float x) {
    float ax = fabsf(x);
    float e  = __expf(ax + ax);                    // exp(2|x|), ~2 ulp
    float r  = 1.0f - __fdividef(2.0f, e + 1.0f);  // inf -> 0 -> r=1 (saturate)
    return copysignf(r, x);
}

// packed f32x2 fma: d = a*b + d  (Blackwell FFMA2)
#define FFMA2(d, a, b) asm("fma.rn.f32x2 %0, %1, %2, %0;" : "+l"(d) : "l"(a), "l"(b))
__device__ __forceinline__ unsigned long long packdup(float v) {
    unsigned long long r;
    asm("mov.b64 %0, {%1, %1};" : "=l"(r) : "r"(__float_as_uint(v)));
    return r;
}

// swizzled row-base byte offset for node n (row = 128B, banks xor'd by n&31)
__device__ __forceinline__ int swb(int n) { return (n << 7) | ((n & 31) << 2); }

__global__ __launch_bounds__(512, 1)
void dgcnn_fused_kernel(const float* __restrict__ x,
                        const int*   __restrict__ esrc,
                        const int*   __restrict__ edst,
                        const float* __restrict__ W0g, const float* __restrict__ b0g,
                        const float* __restrict__ W1g, const float* __restrict__ b1g,
                        const float* __restrict__ W2g, const float* __restrict__ b2g,
                        const float* __restrict__ c1wg, const float* __restrict__ c1bg,
                        const float* __restrict__ c2wg, const float* __restrict__ c2bg,
                        const float* __restrict__ l1wg, const float* __restrict__ l1bg,
                        const float* __restrict__ l2wg, const float* __restrict__ l2bg,
                        float* __restrict__ out)
{
    extern __shared__ char SM[];
    // swizzled 512x32 f32 buffers, 64KB each, 128B-aligned rows
    char*  Ac  = SM;                      // h (pre-scaled by dis)
    char*  Bc  = SM + 65536;              // x staging (matmul1) then x1
    char*  Cc  = SM + 131072;             // x2
    float* dis = (float*)(SM + 196608);   // 512 f
    int*   indptr = (int*)(SM + 198656);  // 514 i32
    unsigned short* csr = (unsigned short*)(SM + 200712);  // 8192 u16, 4B-aligned
    float* x3v = (float*)(SM + 217096);   // 512 f
    char*  U   = SM + 219152;             // 4096 B scratch, 16B-aligned

    const int tid  = threadIdx.x;
    const int lane = tid & 31;
    const int wid  = tid >> 5;          // 0..15
    const int lane4 = lane << 2;
    const int g    = blockIdx.x;
    const int nbase = g * NPG;
    const long ebase = (long)g * EPG;

    // ================= degree count =================
    indptr[tid] = 0;
    if (tid < 2) indptr[512 + tid] = 0;
    __syncthreads();

    #pragma unroll
    for (int i = 0; i < EPG / 512; i++) {
        int e = tid + i * 512;
        int d = edst[ebase + e] - nbase;
        atomicAdd(&indptr[d + 1], 1);
    }
    __syncthreads();

    // dis = rsqrt(deg + 1)  (self loop)
    {
        int cnt = indptr[tid + 1];
        dis[tid] = rsqrtf((float)cnt + 1.0f);
    }

    // ================= exclusive scan -> indptr =================
    {
        int v = indptr[tid + 1];
        #pragma unroll
        for (int off = 1; off < 32; off <<= 1) {
            int n = __shfl_up_sync(0xffffffffu, v, off);
            if (lane >= off) v += n;
        }
        int* wsum = (int*)U;
        if (lane == 31) wsum[wid] = v;
        __syncthreads();
        if (wid == 0) {
            int s = (lane < 16) ? wsum[lane] : 0;
            #pragma unroll
            for (int off = 1; off < 16; off <<= 1) {
                int n = __shfl_up_sync(0xffffffffu, s, off);
                if (lane >= off) s += n;
            }
            if (lane < 16) wsum[lane] = s;
        }
        __syncthreads();
        int prefix = (wid > 0) ? wsum[wid - 1] : 0;
        int incl = v + prefix;
        __syncthreads();
        indptr[tid + 1] = incl;
        if (tid == 0) indptr[0] = 0;
        __syncthreads();
    }

    // ================= CSR fill (entries are pre-swizzled byte offsets) ======
    {
        int* pos = (int*)U;
        pos[tid] = indptr[tid];
        __syncthreads();
        #pragma unroll
        for (int i = 0; i < EPG / 512; i++) {
            int e = tid + i * 512;
            int s = esrc[ebase + e] - nbase;
            int d = edst[ebase + e] - nbase;
            int p = atomicAdd(&pos[d], 1);
            csr[p] = (unsigned short)swb(s);
        }
    }
    // sync at top of matmul1 chunk loop

    const int vt = swb(tid);   // this thread's row-base offset

    // ================= Layer 1 matmul: A = (x_g @ W0) * dis =================
    {
        unsigned long long acc2[16];
        #pragma unroll
        for (int j = 0; j < 16; j++) acc2[j] = 0ull;
        float* Wc = (float*)U;
        const float* xg = x + (size_t)nbase * CIN;
        const unsigned ul = (unsigned)lane * 2052u;  // lane*2048 + lane*4
        for (int cb = 0; cb < 4; cb++) {
            __syncthreads();
            // stage x chunk transposed into B: row=channel (2048B stride, XOR swizzle)
            #pragma unroll
            for (int i = 0; i < 32; i++) {
                int n = i * 16 + wid;
                *(float*)(Bc + (ul ^ (unsigned)(n << 2))) = xg[(size_t)n * CIN + cb * 32 + lane];
            }
            Wc[tid]       = W0g[cb * 1024 + tid];
            Wc[tid + 512] = W0g[cb * 1024 + tid + 512];
            __syncthreads();
            const ulonglong2* W2p = (const ulonglong2*)Wc;
            #pragma unroll 4
            for (int c = 0; c < 32; c++) {
                unsigned long long xx = packdup(*(const float*)(Bc + ((c * 2052) ^ (tid << 2))));
                #pragma unroll
                for (int o4 = 0; o4 < 8; o4++) {
                    ulonglong2 wv = W2p[c * 8 + o4];
                    FFMA2(acc2[o4 * 2 + 0], xx, wv.x);
                    FFMA2(acc2[o4 * 2 + 1], xx, wv.y);
                }
            }
        }
        float dn = dis[tid];
        #pragma unroll
        for (int o4 = 0; o4 < 8; o4++) {
            float2 f0 = *reinterpret_cast<float2*>(&acc2[o4 * 2 + 0]);
            float2 f1 = *reinterpret_cast<float2*>(&acc2[o4 * 2 + 1]);
            *(float*)(Ac + (vt ^ ((o4 * 4 + 0) << 2))) = f0.x * dn;
            *(float*)(Ac + (vt ^ ((o4 * 4 + 1) << 2))) = f0.y * dn;
            *(float*)(Ac + (vt ^ ((o4 * 4 + 2) << 2))) = f1.x * dn;
            *(float*)(Ac + (vt ^ ((o4 * 4 + 3) << 2))) = f1.y * dn;
        }
    }
    __syncthreads();

    // ================= Layer 1 gather -> x1 in B =================
    {
        float bl = b0g[lane];
        for (int n = wid; n < NPG; n += 16) {
            int vn = swb(n);
            float a0 = *(const float*)(Ac + (vn ^ lane4));   // self (pre-scaled)
            float a1 = 0.f, a2 = 0.f, a3 = 0.f;
            int e = indptr[n], end = indptr[n + 1];
            if ((e & 1) && e < end) {
                a1 = *(const float*)(Ac + (csr[e] ^ lane4));
                e++;
            }
            for (; e + 3 < end; e += 4) {
                unsigned w0 = *(const unsigned*)(csr + e);
                unsigned w1 = *(const unsigned*)(csr + e + 2);
                a0 += *(const float*)(Ac + ((int)(w0 & 0xffffu) ^ lane4));
                a1 += *(const float*)(Ac + ((int)(w0 >> 16)     ^ lane4));
                a2 += *(const float*)(Ac + ((int)(w1 & 0xffffu) ^ lane4));
                a3 += *(const float*)(Ac + ((int)(w1 >> 16)     ^ lane4));
            }
            for (; e < end; e++)
                a0 += *(const float*)(Ac + (csr[e] ^ lane4));
            float s = (a0 + a1) + (a2 + a3);
            *(float*)(Bc + (vn ^ lane4)) = tanh_acc(fmaf(s, dis[n], bl));
        }
    }
    __syncthreads();

    // ================= Layer 2 matmul: A = (x1 @ W1) * dis =================
    {
        float* Wc = (float*)U;
        Wc[tid]       = W1g[tid];
        Wc[tid + 512] = W1g[tid + 512];
        __syncthreads();
        unsigned long long acc2[16];
        #pragma unroll
        for (int j = 0; j < 16; j++) acc2[j] = 0ull;
        const ulonglong2* W2p = (const ulonglong2*)Wc;
        #pragma unroll 4
        for (int c = 0; c < 32; c++) {
            unsigned long long xx = packdup(*(const float*)(Bc + (vt ^ (c << 2))));
            #pragma unroll
            for (int o4 = 0; o4 < 8; o4++) {
                ulonglong2 wv = W2p[c * 8 + o4];
                FFMA2(acc2[o4 * 2 + 0], xx, wv.x);
                FFMA2(acc2[o4 * 2 + 1], xx, wv.y);
            }
        }
        float dn = dis[tid];
        #pragma unroll
        for (int o4 = 0; o4 < 8; o4++) {
            float2 f0 = *reinterpret_cast<float2*>(&acc2[o4 * 2 + 0]);
            float2 f1 = *reinterpret_cast<float2*>(&acc2[o4 * 2 + 1]);
            *(float*)(Ac + (vt ^ ((o4 * 4 + 0) << 2))) = f0.x * dn;
            *(float*)(Ac + (vt ^ ((o4 * 4 + 1) << 2))) = f0.y * dn;
            *(float*)(Ac + (vt ^ ((o4 * 4 + 2) << 2))) = f1.x * dn;
            *(float*)(Ac + (vt ^ ((o4 * 4 + 3) << 2))) = f1.y * dn;
        }
    }
    __syncthreads();

    // ================= Layer 2 gather -> x2 in C =================
    {
        float bl = b1g[lane];
        for (int n = wid; n < NPG; n += 16) {
            int vn = swb(n);
            float a0 = *(const float*)(Ac + (vn ^ lane4));
            float a1 = 0.f, a2 = 0.f, a3 = 0.f;
            int e = indptr[n], end = indptr[n + 1];
            if ((e & 1) && e < end) {
                a1 = *(const float*)(Ac + (csr[e] ^ lane4));
                e++;
            }
            for (; e + 3 < end; e += 4) {
                unsigned w0 = *(const unsigned*)(csr + e);
                unsigned w1 = *(const unsigned*)(csr + e + 2);
                a0 += *(const float*)(Ac + ((int)(w0 & 0xffffu) ^ lane4));
                a1 += *(const float*)(Ac + ((int)(w0 >> 16)     ^ lane4));
                a2 += *(const float*)(Ac + ((int)(w1 & 0xffffu) ^ lane4));
                a3 += *(const float*)(Ac + ((int)(w1 >> 16)     ^ lane4));
            }
            for (; e < end; e++)
                a0 += *(const float*)(Ac + (csr[e] ^ lane4));
            float s = (a0 + a1) + (a2 + a3);
            *(float*)(Cc + (vn ^ lane4)) = tanh_acc(fmaf(s, dis[n], bl));
        }
    }
    __syncthreads();

    // ================= Layer 3: h2' = (x2 @ W2)*dis, gather -> x3v ==========
    {
        float w2l = W2g[lane];
        float* h2 = (float*)U;
        for (int n = wid; n < NPG; n += 16) {
            float v = *(const float*)(Cc + (swb(n) ^ lane4)) * w2l;
            #pragma unroll
            for (int off = 16; off; off >>= 1) v += __shfl_down_sync(0xffffffffu, v, off);
            if (lane == 0) h2[n] = v * dis[n];   // pre-scaled
        }
    }
    __syncthreads();
    {
        float* h2 = (float*)U;
        float b2 = b2g[0];
        for (int n = wid; n < NPG; n += 16) {
            int beg = indptr[n], end = indptr[n + 1];
            float p = 0.f;
            for (int e = beg + lane; e < end; e += 32)
                p += h2[csr[e] >> 7];            // recover node id from offset
            #pragma unroll
            for (int off = 16; off; off >>= 1) p += __shfl_down_sync(0xffffffffu, p, off);
            if (lane == 0) {
                float tot = p + h2[n];
                x3v[n] = tanh_acc(fmaf(tot, dis[n], b2));
            }
        }
    }
    __syncthreads();

    // ================= stable top-K: bitonic sort of 512 keys ===============
    unsigned long long* keys = (unsigned long long*)U;
    keys[tid] = ((unsigned long long)ordkey(x3v[tid]) << 32)
              | (unsigned long long)(0xFFFFFFFFu - (unsigned)tid);
    __syncthreads();
    for (int k = 2; k <= 512; k <<= 1) {
        for (int j = k >> 1; j > 0; j >>= 1) {
            int ixj = tid ^ j;
            if (ixj > tid) {
                unsigned long long a = keys[tid], b = keys[ixj];
                bool desc = ((tid & k) == 0);
                if (desc ? (a < b) : (a > b)) { keys[tid] = b; keys[ixj] = a; }
            }
            __syncthreads();
        }
    }

    // ================= tail: conv1 -> maxpool -> conv2 -> lin1 -> lin2 ======
    float* hconv = (float*)Ac;        // 320
    float* hp    = (float*)Ac + 320;  // 160
    float* feat2 = (float*)Ac + 480;  // 192
    float* o1    = (float*)Ac + 672;  // 128
    int*   topn  = (int*)((float*)Ac + 800);  // 20
    float* WS  = (float*)csr;   // CSR dead; 16 KB scratch
    float* c1w = WS;            // 1040
    float* c1b = WS + 1040;     // 16
    float* c2w = WS + 1056;     // 2560
    float* c2b = WS + 3616;     // 32

    for (int i = tid; i < 1040; i += 512) c1w[i] = c1wg[i];
    if (tid < 16) c1b[tid] = c1bg[tid];
    for (int i = tid; i < 2560; i += 512) c2w[i] = c2wg[i];
    if (tid < 32) c2b[tid] = c2bg[tid];
    if (tid < KTOP) topn[tid] = (int)(0xFFFFFFFFu - (unsigned)(keys[tid] & 0xFFFFFFFFull));
    __syncthreads();

    // conv1: [16,K] = relu(pooled . w + b), pooled[k] = [x1|x2|x3](topn[k])
    if (tid < 16 * KTOP) {
        int o = tid & 15, k = tid >> 4;
        int n = topn[k];
        int vn = swb(n);
        float acc = c1b[o];
        const float* wrow = c1w + o * 65;
        #pragma unroll
        for (int c = 0; c < 32; c++)
            acc = fmaf(*(const float*)(Bc + (vn ^ (c << 2))), wrow[c], acc);
        #pragma unroll
        for (int c = 0; c < 32; c++)
            acc = fmaf(*(const float*)(Cc + (vn ^ (c << 2))), wrow[32 + c], acc);
        acc = fmaf(x3v[n], wrow[64], acc);
        hconv[o * KTOP + k] = fmaxf(acc, 0.f);
    }
    __syncthreads();

    // maxpool(2,2): [16,20] -> [16,10]
    if (tid < 160) {
        int o = tid / 10, t = tid % 10;
        hp[o * 10 + t] = fmaxf(hconv[o * KTOP + 2 * t], hconv[o * KTOP + 2 * t + 1]);
    }
    __syncthreads();

    // conv2: Conv1d(16,32,5) valid -> [32,6], relu
    if (tid < 192) {
        int o = tid / 6, t = tid % 6;
        float acc = c2b[o];
        #pragma unroll
        for (int i2 = 0; i2 < 16; i2++)
            #pragma unroll
            for (int j = 0; j < 5; j++)
                acc = fmaf(hp[i2 * 10 + t + j], c2w[(o * 16 + i2) * 5 + j], acc);
        feat2[o * 6 + t] = fmaxf(acc, 0.f);
    }
    __syncthreads();

    // lin1: [192] @ [192,128] + b, relu
    if (tid < 128) {
        float acc = l1bg[tid];
        #pragma unroll 8
        for (int c = 0; c < 192; c++)
            acc = fmaf(feat2[c], l1wg[c * 128 + tid], acc);
        o1[tid] = fmaxf(acc, 0.f);
    }
    __syncthreads();

    // lin2: [128] @ [128,2] + b -> out[g,0..1]
    if (tid < 64) {
        int w = tid >> 5, l = tid & 31;
        float p = o1[l]        * l2wg[l * 2 + w]
                + o1[l + 32]   * l2wg[(l + 32) * 2 + w]
                + o1[l + 64]   * l2wg[(l + 64) * 2 + w]
                + o1[l + 96]   * l2wg[(l + 96) * 2 + w];
        #pragma unroll
        for (int off = 16; off; off >>= 1) p += __shfl_down_sync(0xffffffffu, p, off);
        if (l == 0) out[g * 2 + w] = p + l2bg[w];
    }
}

extern "C" void kernel_launch(void* const* d_in, const int* in_sizes, int n_in,
                              void* d_out, int out_size)
{
    const float* x    = (const float*)d_in[0];
    const int*   ei   = (const int*)d_in[1];
    // d_in[2] = batch (unused; graphs are contiguous)
    const float* W0   = (const float*)d_in[3];
    const float* b0   = (const float*)d_in[4];
    const float* W1   = (const float*)d_in[5];
    const float* b1   = (const float*)d_in[6];
    const float* W2   = (const float*)d_in[7];
    const float* b2   = (const float*)d_in[8];
    const float* c1w  = (const float*)d_in[9];
    const float* c1b  = (const float*)d_in[10];
    const float* c2w  = (const float*)d_in[11];
    const float* c2b  = (const float*)d_in[12];
    const float* l1w  = (const float*)d_in[13];
    const float* l1b  = (const float*)d_in[14];
    const float* l2w  = (const float*)d_in[15];
    const float* l2b  = (const float*)d_in[16];
    float* out = (float*)d_out;

    const long E = (long)in_sizes[1] / 2;   // 4,194,304
    const int* esrc = ei;
    const int* edst = ei + E;

    // layout: A,B,C 64KB swizzled + dis 2048 + indptr 2056 + csr 16384
    //         + x3v 2048 + pad 8 + U 4096 = 223,248 B
    const size_t SMEM = 223248;
    cudaFuncSetAttribute(dgcnn_fused_kernel,
                         cudaFuncAttributeMaxDynamicSharedMemorySize, (int)SMEM);

    dgcnn_fused_kernel<<<NGRAPH, 512, SMEM>>>(
        x, esrc, edst, W0, b0, W1, b1, W2, b2,
        c1w, c1b, c2w, c2b, l1w, l1b, l2w, l2b, out);
}

// round 13
// speedup vs baseline: 1.1747x; 1.1315x over previous
#include <cuda_runtime.h>
#include <math.h>

#define NGRAPH 512
#define NPG    512      // nodes per graph
#define EPG    8192     // edges per graph
#define CIN    128
#define HID    32
#define KTOP   20
#define NT     1024     // threads per CTA (32 warps)

// monotonic float -> uint mapping (order-preserving)
__device__ __forceinline__ unsigned ordkey(float f) {
    unsigned u = __float_as_uint(f);
    return (u & 0x80000000u) ? ~u : (u | 0x80000000u);
}

// Accurate tanh that survives --use_fast_math
__device__ __forceinline__ float tanh_acc(float x) {
    float ax = fabsf(x);
    float e  = __expf(ax + ax);
    float r  = 1.0f - __fdividef(2.0f, e + 1.0f);
    return copysignf(r, x);
}

// packed f32x2 fma: d = a*b + d  (Blackwell FFMA2)
#define FFMA2(d, a, b) asm("fma.rn.f32x2 %0, %1, %2, %0;" : "+l"(d) : "l"(a), "l"(b))
__device__ __forceinline__ unsigned long long packdup(float v) {
    unsigned long long r;
    asm("mov.b64 %0, {%1, %1};" : "=l"(r) : "r"(__float_as_uint(v)));
    return r;
}

// swizzled row-base byte offset for node n (row = 128B, banks xor'd by n&31)
__device__ __forceinline__ int swb(int n) { return (n << 7) | ((n & 31) << 2); }

__global__ __launch_bounds__(NT, 1)
void dgcnn_fused_kernel(const float* __restrict__ x,
                        const int*   __restrict__ esrc,
                        const int*   __restrict__ edst,
                        const float* __restrict__ W0g, const float* __restrict__ b0g,
                        const float* __restrict__ W1g, const float* __restrict__ b1g,
                        const float* __restrict__ W2g, const float* __restrict__ b2g,
                        const float* __restrict__ c1wg, const float* __restrict__ c1bg,
                        const float* __restrict__ c2wg, const float* __restrict__ c2bg,
                        const float* __restrict__ l1wg, const float* __restrict__ l1bg,
                        const float* __restrict__ l2wg, const float* __restrict__ l2bg,
                        float* __restrict__ out)
{
    extern __shared__ char SM[];
    char*  Ac  = SM;                      // h (pre-scaled by dis), swizzled 512x32 f32
    char*  Bc  = SM + 65536;              // x staging (matmul1) then x1
    char*  Cc  = SM + 131072;             // x2
    float* dis = (float*)(SM + 196608);   // 512 f
    int*   indptr = (int*)(SM + 198656);  // 514 i32
    unsigned short* csr = (unsigned short*)(SM + 200712);  // 8192 u16
    float* x3v = (float*)(SM + 217096);   // 512 f
    char*  U   = SM + 219152;             // 4096 B scratch, 16B-aligned

    const int tid  = threadIdx.x;
    const int lane = tid & 31;
    const int wid  = tid >> 5;          // 0..31
    const int lane4 = lane << 2;
    const int g    = blockIdx.x;
    const int nbase = g * NPG;
    const long ebase = (long)g * EPG;

    // ================= degree count =================
    if (tid < 514) indptr[tid] = 0;
    __syncthreads();

    #pragma unroll
    for (int i = 0; i < EPG / NT; i++) {
        int e = tid + i * NT;
        int d = edst[ebase + e] - nbase;
        atomicAdd(&indptr[d + 1], 1);
    }
    __syncthreads();

    // dis = rsqrt(deg + 1)
    if (tid < 512) dis[tid] = rsqrtf((float)indptr[tid + 1] + 1.0f);

    // ================= exclusive scan -> indptr (512 values) =================
    {
        int v = (tid < 512) ? indptr[tid + 1] : 0;
        #pragma unroll
        for (int off = 1; off < 32; off <<= 1) {
            int n = __shfl_up_sync(0xffffffffu, v, off);
            if (lane >= off) v += n;
        }
        int* wsum = (int*)U;
        if (lane == 31 && wid < 16) wsum[wid] = v;
        __syncthreads();
        if (wid == 0) {
            int s = (lane < 16) ? wsum[lane] : 0;
            #pragma unroll
            for (int off = 1; off < 16; off <<= 1) {
                int n = __shfl_up_sync(0xffffffffu, s, off);
                if (lane >= off) s += n;
            }
            if (lane < 16) wsum[lane] = s;
        }
        __syncthreads();
        int incl = 0;
        if (tid < 512) {
            int prefix = (wid > 0) ? wsum[wid - 1] : 0;
            incl = v + prefix;
        }
        __syncthreads();            // everyone done reading wsum
        if (tid < 512) indptr[tid + 1] = incl;
        if (tid == 0) indptr[0] = 0;
        __syncthreads();
    }

    // ================= CSR fill (entries are pre-swizzled byte offsets) ======
    {
        int* pos = (int*)U;
        if (tid < 512) pos[tid] = indptr[tid];
        __syncthreads();
        #pragma unroll
        for (int i = 0; i < EPG / NT; i++) {
            int e = tid + i * NT;
            int s = esrc[ebase + e] - nbase;
            int d = edst[ebase + e] - nbase;
            int p = atomicAdd(&pos[d], 1);
            csr[p] = (unsigned short)swb(s);
        }
    }
    // sync at top of matmul1 chunk loop

    const int node = tid >> 1;          // matmul: pair-split over channels
    const int half = tid & 1;           // 0: ch 0-15, 1: ch 16-31
    const int vnode = swb(node);

    // ================= Layer 1 matmul: A = (x_g @ W0) * dis =================
    {
        unsigned long long acc2[8];
        #pragma unroll
        for (int j = 0; j < 8; j++) acc2[j] = 0ull;
        float* Wc = (float*)U;
        const float* xg = x + (size_t)nbase * CIN;
        const unsigned ul = (unsigned)lane * 2052u;   // ch*2048 + ch*4
        for (int cb = 0; cb < 4; cb++) {
            __syncthreads();
            // stage x chunk transposed into B: row=channel (2048B stride, XOR swizzle)
            #pragma unroll
            for (int i = 0; i < 16; i++) {
                int n = i * 32 + wid;
                *(float*)(Bc + (ul ^ (unsigned)(n << 2))) = xg[(size_t)n * CIN + cb * 32 + lane];
            }
            Wc[tid] = W0g[cb * 1024 + tid];
            __syncthreads();
            const ulonglong2* W2p = (const ulonglong2*)Wc;
            #pragma unroll 4
            for (int c = 0; c < 32; c++) {
                unsigned long long xx = packdup(*(const float*)(Bc + ((c * 2052) ^ (node << 2))));
                #pragma unroll
                for (int o4 = 0; o4 < 4; o4++) {
                    ulonglong2 wv = W2p[c * 8 + half * 4 + o4];
                    FFMA2(acc2[o4 * 2 + 0], xx, wv.x);
                    FFMA2(acc2[o4 * 2 + 1], xx, wv.y);
                }
            }
        }
        float dn = dis[node];
        int cbase = half << 4;
        #pragma unroll
        for (int o4 = 0; o4 < 4; o4++) {
            float2 f0 = *reinterpret_cast<float2*>(&acc2[o4 * 2 + 0]);
            float2 f1 = *reinterpret_cast<float2*>(&acc2[o4 * 2 + 1]);
            *(float*)(Ac + (vnode ^ ((cbase + o4 * 4 + 0) << 2))) = f0.x * dn;
            *(float*)(Ac + (vnode ^ ((cbase + o4 * 4 + 1) << 2))) = f0.y * dn;
            *(float*)(Ac + (vnode ^ ((cbase + o4 * 4 + 2) << 2))) = f1.x * dn;
            *(float*)(Ac + (vnode ^ ((cbase + o4 * 4 + 3) << 2))) = f1.y * dn;
        }
    }
    __syncthreads();

    // ================= Layer 1 gather -> x1 in B =================
    {
        float bl = b0g[lane];
        for (int n = wid; n < NPG; n += 32) {
            int vn = swb(n);
            float a0 = *(const float*)(Ac + (vn ^ lane4));   // self (pre-scaled)
            float a1 = 0.f, a2 = 0.f, a3 = 0.f;
            int e = indptr[n], end = indptr[n + 1];
            if ((e & 1) && e < end) {
                a1 = *(const float*)(Ac + (csr[e] ^ lane4));
                e++;
            }
            for (; e + 3 < end; e += 4) {
                unsigned w0 = *(const unsigned*)(csr + e);
                unsigned w1 = *(const unsigned*)(csr + e + 2);
                a0 += *(const float*)(Ac + ((int)(w0 & 0xffffu) ^ lane4));
                a1 += *(const float*)(Ac + ((int)(w0 >> 16)     ^ lane4));
                a2 += *(const float*)(Ac + ((int)(w1 & 0xffffu) ^ lane4));
                a3 += *(const float*)(Ac + ((int)(w1 >> 16)     ^ lane4));
            }
            for (; e < end; e++)
                a0 += *(const float*)(Ac + (csr[e] ^ lane4));
            float s = (a0 + a1) + (a2 + a3);
            *(float*)(Bc + (vn ^ lane4)) = tanh_acc(fmaf(s, dis[n], bl));
        }
    }
    __syncthreads();

    // ================= Layer 2 matmul: A = (x1 @ W1) * dis =================
    {
        float* Wc = (float*)U;
        Wc[tid] = W1g[tid];
        __syncthreads();
        unsigned long long acc2[8];
        #pragma unroll
        for (int j = 0; j < 8; j++) acc2[j] = 0ull;
        const ulonglong2* W2p = (const ulonglong2*)Wc;
        #pragma unroll 4
        for (int c = 0; c < 32; c++) {
            unsigned long long xx = packdup(*(const float*)(Bc + (vnode ^ (c << 2))));
            #pragma unroll
            for (int o4 = 0; o4 < 4; o4++) {
                ulonglong2 wv = W2p[c * 8 + half * 4 + o4];
                FFMA2(acc2[o4 * 2 + 0], xx, wv.x);
                FFMA2(acc2[o4 * 2 + 1], xx, wv.y);
            }
        }
        __syncthreads();   // Wc (U) reused later; also order vs next stage
        float dn = dis[node];
        int cbase = half << 4;
        #pragma unroll
        for (int o4 = 0; o4 < 4; o4++) {
            float2 f0 = *reinterpret_cast<float2*>(&acc2[o4 * 2 + 0]);
            float2 f1 = *reinterpret_cast<float2*>(&acc2[o4 * 2 + 1]);
            *(float*)(Ac + (vnode ^ ((cbase + o4 * 4 + 0) << 2))) = f0.x * dn;
            *(float*)(Ac + (vnode ^ ((cbase + o4 * 4 + 1) << 2))) = f0.y * dn;
            *(float*)(Ac + (vnode ^ ((cbase + o4 * 4 + 2) << 2))) = f1.x * dn;
            *(float*)(Ac + (vnode ^ ((cbase + o4 * 4 + 3) << 2))) = f1.y * dn;
        }
    }
    __syncthreads();

    // ================= Layer 2 gather -> x2 in C =================
    {
        float bl = b1g[lane];
        for (int n = wid; n < NPG; n += 32) {
            int vn = swb(n);
            float a0 = *(const float*)(Ac + (vn ^ lane4));
            float a1 = 0.f, a2 = 0.f, a3 = 0.f;
            int e = indptr[n], end = indptr[n + 1];
            if ((e & 1) && e < end) {
                a1 = *(const float*)(Ac + (csr[e] ^ lane4));
                e++;
            }
            for (; e + 3 < end; e += 4) {
                unsigned w0 = *(const unsigned*)(csr + e);
                unsigned w1 = *(const unsigned*)(csr + e + 2);
                a0 += *(const float*)(Ac + ((int)(w0 & 0xffffu) ^ lane4));
                a1 += *(const float*)(Ac + ((int)(w0 >> 16)     ^ lane4));
                a2 += *(const float*)(Ac + ((int)(w1 & 0xffffu) ^ lane4));
                a3 += *(const float*)(Ac + ((int)(w1 >> 16)     ^ lane4));
            }
            for (; e < end; e++)
                a0 += *(const float*)(Ac + (csr[e] ^ lane4));
            float s = (a0 + a1) + (a2 + a3);
            *(float*)(Cc + (vn ^ lane4)) = tanh_acc(fmaf(s, dis[n], bl));
        }
    }
    __syncthreads();

    // ================= Layer 3: h2' = (x2 @ W2)*dis, gather -> x3v ==========
    {
        float w2l = W2g[lane];
        float* h2 = (float*)U;
        for (int n = wid; n < NPG; n += 32) {
            float v = *(const float*)(Cc + (swb(n) ^ lane4)) * w2l;
            #pragma unroll
            for (int off = 16; off; off >>= 1) v += __shfl_down_sync(0xffffffffu, v, off);
            if (lane == 0) h2[n] = v * dis[n];   // pre-scaled
        }
    }
    __syncthreads();
    {
        float* h2 = (float*)U;
        float b2 = b2g[0];
        for (int n = wid; n < NPG; n += 32) {
            int beg = indptr[n], end = indptr[n + 1];
            float p = 0.f;
            for (int e = beg + lane; e < end; e += 32)
                p += h2[csr[e] >> 7];            // recover node id from offset
            #pragma unroll
            for (int off = 16; off; off >>= 1) p += __shfl_down_sync(0xffffffffu, p, off);
            if (lane == 0) {
                float tot = p + h2[n];
                x3v[n] = tanh_acc(fmaf(tot, dis[n], b2));
            }
        }
    }
    __syncthreads();

    // ================= stable top-K: bitonic sort of 512 keys ===============
    unsigned long long* keys = (unsigned long long*)U;
    if (tid < 512)
        keys[tid] = ((unsigned long long)ordkey(x3v[tid]) << 32)
                  | (unsigned long long)(0xFFFFFFFFu - (unsigned)tid);
    __syncthreads();
    for (int k = 2; k <= 512; k <<= 1) {
        for (int j = k >> 1; j > 0; j >>= 1) {
            if (tid < 512) {
                int ixj = tid ^ j;
                if (ixj > tid) {
                    unsigned long long a = keys[tid], b = keys[ixj];
                    bool desc = ((tid & k) == 0);
                    if (desc ? (a < b) : (a > b)) { keys[tid] = b; keys[ixj] = a; }
                }
            }
            __syncthreads();
        }
    }

    // ================= tail: conv1 -> maxpool -> conv2 -> lin1 -> lin2 ======
    float* hconv = (float*)Ac;        // 320
    float* hp    = (float*)Ac + 320;  // 160
    float* feat2 = (float*)Ac + 480;  // 192
    float* o1    = (float*)Ac + 672;  // 128
    int*   topn  = (int*)((float*)Ac + 800);  // 20
    float* WS  = (float*)csr;   // CSR dead; 16 KB scratch
    float* c1w = WS;            // 1040
    float* c1b = WS + 1040;     // 16
    float* c2w = WS + 1056;     // 2560
    float* c2b = WS + 3616;     // 32

    for (int i = tid; i < 1040; i += NT) c1w[i] = c1wg[i];   // FIX: cover 1024..1039
    if (tid < 16) c1b[tid] = c1bg[tid];
    for (int i = tid; i < 2560; i += NT) c2w[i] = c2wg[i];
    if (tid < 32) c2b[tid] = c2bg[tid];
    if (tid < KTOP) topn[tid] = (int)(0xFFFFFFFFu - (unsigned)(keys[tid] & 0xFFFFFFFFull));
    __syncthreads();

    // conv1: [16,K] = relu(pooled . w + b)
    if (tid < 16 * KTOP) {
        int o = tid & 15, k = tid >> 4;
        int n = topn[k];
        int vn = swb(n);
        float acc = c1b[o];
        const float* wrow = c1w + o * 65;
        #pragma unroll
        for (int c = 0; c < 32; c++)
            acc = fmaf(*(const float*)(Bc + (vn ^ (c << 2))), wrow[c], acc);
        #pragma unroll
        for (int c = 0; c < 32; c++)
            acc = fmaf(*(const float*)(Cc + (vn ^ (c << 2))), wrow[32 + c], acc);
        acc = fmaf(x3v[n], wrow[64], acc);
        hconv[o * KTOP + k] = fmaxf(acc, 0.f);
    }
    __syncthreads();

    // maxpool(2,2): [16,20] -> [16,10]
    if (tid < 160) {
        int o = tid / 10, t = tid % 10;
        hp[o * 10 + t] = fmaxf(hconv[o * KTOP + 2 * t], hconv[o * KTOP + 2 * t + 1]);
    }
    __syncthreads();

    // conv2: Conv1d(16,32,5) valid -> [32,6], relu
    if (tid < 192) {
        int o = tid / 6, t = tid % 6;
        float acc = c2b[o];
        #pragma unroll
        for (int i2 = 0; i2 < 16; i2++)
            #pragma unroll
            for (int j = 0; j < 5; j++)
                acc = fmaf(hp[i2 * 10 + t + j], c2w[(o * 16 + i2) * 5 + j], acc);
        feat2[o * 6 + t] = fmaxf(acc, 0.f);
    }
    __syncthreads();

    // lin1: [192] @ [192,128] + b, relu
    if (tid < 128) {
        float acc = l1bg[tid];
        #pragma unroll 8
        for (int c = 0; c < 192; c++)
            acc = fmaf(feat2[c], l1wg[c * 128 + tid], acc);
        o1[tid] = fmaxf(acc, 0.f);
    }
    __syncthreads();

    // lin2: [128] @ [128,2] + b -> out[g,0..1]
    if (tid < 64) {
        int w = tid >> 5, l = tid & 31;
        float p = o1[l]        * l2wg[l * 2 + w]
                + o1[l + 32]   * l2wg[(l + 32) * 2 + w]
                + o1[l + 64]   * l2wg[(l + 64) * 2 + w]
                + o1[l + 96]   * l2wg[(l + 96) * 2 + w];
        #pragma unroll
        for (int off = 16; off; off >>= 1) p += __shfl_down_sync(0xffffffffu, p, off);
        if (l == 0) out[g * 2 + w] = p + l2bg[w];
    }
}

extern "C" void kernel_launch(void* const* d_in, const int* in_sizes, int n_in,
                              void* d_out, int out_size)
{
    const float* x    = (const float*)d_in[0];
    const int*   ei   = (const int*)d_in[1];
    // d_in[2] = batch (unused; graphs are contiguous)
    const float* W0   = (const float*)d_in[3];
    const float* b0   = (const float*)d_in[4];
    const float* W1   = (const float*)d_in[5];
    const float* b1   = (const float*)d_in[6];
    const float* W2   = (const float*)d_in[7];
    const float* b2   = (const float*)d_in[8];
    const float* c1w  = (const float*)d_in[9];
    const float* c1b  = (const float*)d_in[10];
    const float* c2w  = (const float*)d_in[11];
    const float* c2b  = (const float*)d_in[12];
    const float* l1w  = (const float*)d_in[13];
    const float* l1b  = (const float*)d_in[14];
    const float* l2w  = (const float*)d_in[15];
    const float* l2b  = (const float*)d_in[16];
    float* out = (float*)d_out;

    const long E = (long)in_sizes[1] / 2;   // 4,194,304
    const int* esrc = ei;
    const int* edst = ei + E;

    const size_t SMEM = 223248;
    cudaFuncSetAttribute(dgcnn_fused_kernel,
                         cudaFuncAttributeMaxDynamicSharedMemorySize, (int)SMEM);

    dgcnn_fused_kernel<<<NGRAPH, NT, SMEM>>>(
        x, esrc, edst, W0, b0, W1, b1, W2, b2,
        c1w, c1b, c2w, c2b, l1w, l1b, l2w, l2b, out);
}

// round 14
// speedup vs baseline: 1.1803x; 1.0048x over previous
#include <cuda_runtime.h>
#include <math.h>

#define NGRAPH 512
#define NPG    512      // nodes per graph
#define EPG    8192     // edges per graph
#define CIN    128
#define HID    32
#define KTOP   20
#define NT     1024     // threads per CTA (32 warps)

// monotonic float -> uint mapping (order-preserving)
__device__ __forceinline__ unsigned ordkey(float f) {
    unsigned u = __float_as_uint(f);
    return (u & 0x80000000u) ? ~u : (u | 0x80000000u);
}

// Accurate tanh that survives --use_fast_math
__device__ __forceinline__ float tanh_acc(float x) {
    float ax = fabsf(x);
    float e  = __expf(ax + ax);
    float r  = 1.0f - __fdividef(2.0f, e + 1.0f);
    return copysignf(r, x);
}

// packed f32x2 fma: d = a*b + d  (Blackwell FFMA2)
#define FFMA2(d, a, b) asm("fma.rn.f32x2 %0, %1, %2, %0;" : "+l"(d) : "l"(a), "l"(b))
// packed f32x2 add: a += v
#define ADDF2(a, v)    asm("add.rn.f32x2 %0, %0, %1;" : "+l"(a) : "l"(v))
__device__ __forceinline__ unsigned long long packdup(float v) {
    unsigned long long r;
    asm("mov.b64 %0, {%1, %1};" : "=l"(r) : "r"(__float_as_uint(v)));
    return r;
}

// swizzled row-base byte offset for node n. Row = 128B. Swizzle constant
// s = (n&30) ^ ((n&1)<<4) is EVEN (preserves channel-pair order for LDS.64)
// and distinct for 16 consecutive nodes (conflict-free epilogue writes).
__device__ __forceinline__ int swb(int n) {
    int s = (n & 30) ^ ((n & 1) << 4);
    return (n << 7) | (s << 2);
}

__global__ __launch_bounds__(NT, 1)
void dgcnn_fused_kernel(const float* __restrict__ x,
                        const int*   __restrict__ esrc,
                        const int*   __restrict__ edst,
                        const float* __restrict__ W0g, const float* __restrict__ b0g,
                        const float* __restrict__ W1g, const float* __restrict__ b1g,
                        const float* __restrict__ W2g, const float* __restrict__ b2g,
                        const float* __restrict__ c1wg, const float* __restrict__ c1bg,
                        const float* __restrict__ c2wg, const float* __restrict__ c2bg,
                        const float* __restrict__ l1wg, const float* __restrict__ l1bg,
                        const float* __restrict__ l2wg, const float* __restrict__ l2bg,
                        float* __restrict__ out)
{
    extern __shared__ char SM[];
    char*  Ac  = SM;                      // h (pre-scaled by dis), swizzled 512x32 f32
    char*  Bc  = SM + 65536;              // x staging (matmul1) then x1
    char*  Cc  = SM + 131072;             // x2
    float* dis = (float*)(SM + 196608);   // 512 f
    int*   indptr = (int*)(SM + 198656);  // 514 i32
    unsigned short* csr = (unsigned short*)(SM + 200712);  // 8192 u16
    float* x3v = (float*)(SM + 217096);   // 512 f
    char*  U   = SM + 219152;             // 4096 B scratch, 16B-aligned

    const int tid  = threadIdx.x;
    const int lane = tid & 31;
    const int wid  = tid >> 5;          // 0..31
    const int g    = blockIdx.x;
    const int nbase = g * NPG;
    const long ebase = (long)g * EPG;

    // gather constants: half-warp-per-edge scheme
    const int hl   = lane & 15;         // channel-pair index (2 ch / lane)
    const int half = lane >> 4;         // 0: even edge, 1: odd edge
    const unsigned u8 = (unsigned)hl << 3;               // 8B unit offset
    const unsigned psel = half ? 0x4432u : 0x4410u;      // PRMT: extract u16

    // ================= degree count =================
    if (tid < 514) indptr[tid] = 0;
    __syncthreads();

    #pragma unroll
    for (int i = 0; i < EPG / NT; i++) {
        int e = tid + i * NT;
        int d = edst[ebase + e] - nbase;
        atomicAdd(&indptr[d + 1], 1);
    }
    __syncthreads();

    // dis = rsqrt(deg + 1)
    if (tid < 512) dis[tid] = rsqrtf((float)indptr[tid + 1] + 1.0f);

    // ================= exclusive scan -> indptr (512 values) =================
    {
        int v = (tid < 512) ? indptr[tid + 1] : 0;
        #pragma unroll
        for (int off = 1; off < 32; off <<= 1) {
            int n = __shfl_up_sync(0xffffffffu, v, off);
            if (lane >= off) v += n;
        }
        int* wsum = (int*)U;
        if (lane == 31 && wid < 16) wsum[wid] = v;
        __syncthreads();
        if (wid == 0) {
            int s = (lane < 16) ? wsum[lane] : 0;
            #pragma unroll
            for (int off = 1; off < 16; off <<= 1) {
                int n = __shfl_up_sync(0xffffffffu, s, off);
                if (lane >= off) s += n;
            }
            if (lane < 16) wsum[lane] = s;
        }
        __syncthreads();
        int incl = 0;
        if (tid < 512) {
            int prefix = (wid > 0) ? wsum[wid - 1] : 0;
            incl = v + prefix;
        }
        __syncthreads();            // everyone done reading wsum
        if (tid < 512) indptr[tid + 1] = incl;
        if (tid == 0) indptr[0] = 0;
        __syncthreads();
    }

    // ================= CSR fill (entries are pre-swizzled byte offsets) ======
    {
        int* pos = (int*)U;
        if (tid < 512) pos[tid] = indptr[tid];
        __syncthreads();
        #pragma unroll
        for (int i = 0; i < EPG / NT; i++) {
            int e = tid + i * NT;
            int s = esrc[ebase + e] - nbase;
            int d = edst[ebase + e] - nbase;
            int p = atomicAdd(&pos[d], 1);
            csr[p] = (unsigned short)swb(s);
        }
    }
    // sync at top of matmul1 chunk loop

    const int node = tid >> 1;          // matmul: pair-split over channels
    const int mhalf = tid & 1;          // 0: ch 0-15, 1: ch 16-31
    const int vnode = swb(node);

    // ================= Layer 1 matmul: A = (x_g @ W0) * dis =================
    {
        unsigned long long acc2[8];
        #pragma unroll
        for (int j = 0; j < 8; j++) acc2[j] = 0ull;
        float* Wc = (float*)U;
        const float* xg = x + (size_t)nbase * CIN;
        const unsigned ul = (unsigned)lane * 2052u;   // ch*2048 + ch*4
        for (int cb = 0; cb < 4; cb++) {
            __syncthreads();
            // stage x chunk transposed into B: row=channel (2048B stride, XOR swizzle)
            #pragma unroll
            for (int i = 0; i < 16; i++) {
                int n = i * 32 + wid;
                *(float*)(Bc + (ul ^ (unsigned)(n << 2))) = xg[(size_t)n * CIN + cb * 32 + lane];
            }
            Wc[tid] = W0g[cb * 1024 + tid];
            __syncthreads();
            const ulonglong2* W2p = (const ulonglong2*)Wc;
            #pragma unroll 4
            for (int c = 0; c < 32; c++) {
                unsigned long long xx = packdup(*(const float*)(Bc + ((c * 2052) ^ (node << 2))));
                #pragma unroll
                for (int o4 = 0; o4 < 4; o4++) {
                    ulonglong2 wv = W2p[c * 8 + mhalf * 4 + o4];
                    FFMA2(acc2[o4 * 2 + 0], xx, wv.x);
                    FFMA2(acc2[o4 * 2 + 1], xx, wv.y);
                }
            }
        }
        float dn = dis[node];
        int cbase = mhalf << 4;
        #pragma unroll
        for (int o4 = 0; o4 < 4; o4++) {
            float2 f0 = *reinterpret_cast<float2*>(&acc2[o4 * 2 + 0]);
            float2 f1 = *reinterpret_cast<float2*>(&acc2[o4 * 2 + 1]);
            *(float*)(Ac + (vnode ^ ((cbase + o4 * 4 + 0) << 2))) = f0.x * dn;
            *(float*)(Ac + (vnode ^ ((cbase + o4 * 4 + 1) << 2))) = f0.y * dn;
            *(float*)(Ac + (vnode ^ ((cbase + o4 * 4 + 2) << 2))) = f1.x * dn;
            *(float*)(Ac + (vnode ^ ((cbase + o4 * 4 + 3) << 2))) = f1.y * dn;
        }
    }
    __syncthreads();

    // ================= Layer 1 gather -> x1 in B (2 edges / instruction) ====
    {
        float bla = b0g[2 * hl], blb = b0g[2 * hl + 1];
        for (int n = wid; n < NPG; n += 32) {
            int vn = swb(n);
            unsigned long long acc = 0ull;
            if (!half) acc = *(const unsigned long long*)(Ac + ((unsigned)vn ^ u8));  // self
            int e = indptr[n], end = indptr[n + 1];
            if (e < end && (e & 1)) {                     // peel to even e
                if (!half) {
                    unsigned long long v = *(const unsigned long long*)(Ac + ((unsigned)csr[e] ^ u8));
                    ADDF2(acc, v);
                }
                e++;
            }
            for (; e + 3 < end; e += 4) {
                unsigned w0 = *(const unsigned*)(csr + e);
                unsigned w1 = *(const unsigned*)(csr + e + 2);
                unsigned vo0 = __byte_perm(w0, 0, psel);
                unsigned vo1 = __byte_perm(w1, 0, psel);
                unsigned long long v0 = *(const unsigned long long*)(Ac + (vo0 ^ u8));
                unsigned long long v1 = *(const unsigned long long*)(Ac + (vo1 ^ u8));
                ADDF2(acc, v0);
                ADDF2(acc, v1);
            }
            if (e + 1 < end) {
                unsigned w0 = *(const unsigned*)(csr + e);
                unsigned vo0 = __byte_perm(w0, 0, psel);
                unsigned long long v0 = *(const unsigned long long*)(Ac + (vo0 ^ u8));
                ADDF2(acc, v0);
                e += 2;
            }
            if (e < end && !half) {                       // tail single edge
                unsigned long long v = *(const unsigned long long*)(Ac + ((unsigned)csr[e] ^ u8));
                ADDF2(acc, v);
            }
            // merge halves
            float ax = __uint_as_float((unsigned)acc);
            float ay = __uint_as_float((unsigned)(acc >> 32));
            ax += __shfl_xor_sync(0xffffffffu, ax, 16);
            ay += __shfl_xor_sync(0xffffffffu, ay, 16);
            if (!half) {
                float dn = dis[n];
                float2 r;
                r.x = tanh_acc(fmaf(ax, dn, bla));
                r.y = tanh_acc(fmaf(ay, dn, blb));
                *(float2*)(Bc + ((unsigned)vn ^ u8)) = r;
            }
        }
    }
    __syncthreads();

    // ================= Layer 2 matmul: A = (x1 @ W1) * dis =================
    {
        float* Wc = (float*)U;
        Wc[tid] = W1g[tid];
        __syncthreads();
        unsigned long long acc2[8];
        #pragma unroll
        for (int j = 0; j < 8; j++) acc2[j] = 0ull;
        const ulonglong2* W2p = (const ulonglong2*)Wc;
        #pragma unroll 4
        for (int c = 0; c < 32; c++) {
            unsigned long long xx = packdup(*(const float*)(Bc + (vnode ^ (c << 2))));
            #pragma unroll
            for (int o4 = 0; o4 < 4; o4++) {
                ulonglong2 wv = W2p[c * 8 + mhalf * 4 + o4];
                FFMA2(acc2[o4 * 2 + 0], xx, wv.x);
                FFMA2(acc2[o4 * 2 + 1], xx, wv.y);
            }
        }
        __syncthreads();   // Wc (U) reused later; also order vs next stage
        float dn = dis[node];
        int cbase = mhalf << 4;
        #pragma unroll
        for (int o4 = 0; o4 < 4; o4++) {
            float2 f0 = *reinterpret_cast<float2*>(&acc2[o4 * 2 + 0]);
            float2 f1 = *reinterpret_cast<float2*>(&acc2[o4 * 2 + 1]);
            *(float*)(Ac + (vnode ^ ((cbase + o4 * 4 + 0) << 2))) = f0.x * dn;
            *(float*)(Ac + (vnode ^ ((cbase + o4 * 4 + 1) << 2))) = f0.y * dn;
            *(float*)(Ac + (vnode ^ ((cbase + o4 * 4 + 2) << 2))) = f1.x * dn;
            *(float*)(Ac + (vnode ^ ((cbase + o4 * 4 + 3) << 2))) = f1.y * dn;
        }
    }
    __syncthreads();

    // ================= Layer 2 gather -> x2 in C =================
    {
        float bla = b1g[2 * hl], blb = b1g[2 * hl + 1];
        for (int n = wid; n < NPG; n += 32) {
            int vn = swb(n);
            unsigned long long acc = 0ull;
            if (!half) acc = *(const unsigned long long*)(Ac + ((unsigned)vn ^ u8));
            int e = indptr[n], end = indptr[n + 1];
            if (e < end && (e & 1)) {
                if (!half) {
                    unsigned long long v = *(const unsigned long long*)(Ac + ((unsigned)csr[e] ^ u8));
                    ADDF2(acc, v);
                }
                e++;
            }
            for (; e + 3 < end; e += 4) {
                unsigned w0 = *(const unsigned*)(csr + e);
                unsigned w1 = *(const unsigned*)(csr + e + 2);
                unsigned vo0 = __byte_perm(w0, 0, psel);
                unsigned vo1 = __byte_perm(w1, 0, psel);
                unsigned long long v0 = *(const unsigned long long*)(Ac + (vo0 ^ u8));
                unsigned long long v1 = *(const unsigned long long*)(Ac + (vo1 ^ u8));
                ADDF2(acc, v0);
                ADDF2(acc, v1);
            }
            if (e + 1 < end) {
                unsigned w0 = *(const unsigned*)(csr + e);
                unsigned vo0 = __byte_perm(w0, 0, psel);
                unsigned long long v0 = *(const unsigned long long*)(Ac + (vo0 ^ u8));
                ADDF2(acc, v0);
                e += 2;
            }
            if (e < end && !half) {
                unsigned long long v = *(const unsigned long long*)(Ac + ((unsigned)csr[e] ^ u8));
                ADDF2(acc, v);
            }
            float ax = __uint_as_float((unsigned)acc);
            float ay = __uint_as_float((unsigned)(acc >> 32));
            ax += __shfl_xor_sync(0xffffffffu, ax, 16);
            ay += __shfl_xor_sync(0xffffffffu, ay, 16);
            if (!half) {
                float dn = dis[n];
                float2 r;
                r.x = tanh_acc(fmaf(ax, dn, bla));
                r.y = tanh_acc(fmaf(ay, dn, blb));
                *(float2*)(Cc + ((unsigned)vn ^ u8)) = r;
            }
        }
    }
    __syncthreads();

    // ================= Layer 3: h2' = (x2 @ W2)*dis, gather -> x3v ==========
    {
        float w2l = W2g[lane];
        float* h2 = (float*)U;
        for (int n = wid; n < NPG; n += 32) {
            float v = *(const float*)(Cc + (swb(n) ^ (lane << 2))) * w2l;
            #pragma unroll
            for (int off = 16; off; off >>= 1) v += __shfl_down_sync(0xffffffffu, v, off);
            if (lane == 0) h2[n] = v * dis[n];   // pre-scaled
        }
    }
    __syncthreads();
    {
        float* h2 = (float*)U;
        float b2 = b2g[0];
        for (int n = wid; n < NPG; n += 32) {
            int beg = indptr[n], end = indptr[n + 1];
            float p = 0.f;
            for (int e = beg + lane; e < end; e += 32)
                p += h2[csr[e] >> 7];            // recover node id from offset
            #pragma unroll
            for (int off = 16; off; off >>= 1) p += __shfl_down_sync(0xffffffffu, p, off);
            if (lane == 0) {
                float tot = p + h2[n];
                x3v[n] = tanh_acc(fmaf(tot, dis[n], b2));
            }
        }
    }
    __syncthreads();

    // ================= stable top-K: bitonic sort of 512 keys ===============
    unsigned long long* keys = (unsigned long long*)U;
    if (tid < 512)
        keys[tid] = ((unsigned long long)ordkey(x3v[tid]) << 32)
                  | (unsigned long long)(0xFFFFFFFFu - (unsigned)tid);
    __syncthreads();
    for (int k = 2; k <= 512; k <<= 1) {
        for (int j = k >> 1; j > 0; j >>= 1) {
            if (tid < 512) {
                int ixj = tid ^ j;
                if (ixj > tid) {
                    unsigned long long a = keys[tid], b = keys[ixj];
                    bool desc = ((tid & k) == 0);
                    if (desc ? (a < b) : (a > b)) { keys[tid] = b; keys[ixj] = a; }
                }
            }
            __syncthreads();
        }
    }

    // ================= tail: conv1 -> maxpool -> conv2 -> lin1 -> lin2 ======
    float* hconv = (float*)Ac;        // 320
    float* hp    = (float*)Ac + 320;  // 160
    float* feat2 = (float*)Ac + 480;  // 192
    float* o1    = (float*)Ac + 672;  // 128
    int*   topn  = (int*)((float*)Ac + 800);  // 20
    float* WS  = (float*)csr;   // CSR dead; 16 KB scratch
    float* c1w = WS;            // 1040
    float* c1b = WS + 1040;     // 16
    float* c2w = WS + 1056;     // 2560
    float* c2b = WS + 3616;     // 32

    for (int i = tid; i < 1040; i += NT) c1w[i] = c1wg[i];
    if (tid < 16) c1b[tid] = c1bg[tid];
    for (int i = tid; i < 2560; i += NT) c2w[i] = c2wg[i];
    if (tid < 32) c2b[tid] = c2bg[tid];
    if (tid < KTOP) topn[tid] = (int)(0xFFFFFFFFu - (unsigned)(keys[tid] & 0xFFFFFFFFull));
    __syncthreads();

    // conv1: [16,K] = relu(pooled . w + b)
    if (tid < 16 * KTOP) {
        int o = tid & 15, k = tid >> 4;
        int n = topn[k];
        int vn = swb(n);
        float acc = c1b[o];
        const float* wrow = c1w + o * 65;
        #pragma unroll
        for (int c = 0; c < 32; c++)
            acc = fmaf(*(const float*)(Bc + (vn ^ (c << 2))), wrow[c], acc);
        #pragma unroll
        for (int c = 0; c < 32; c++)
            acc = fmaf(*(const float*)(Cc + (vn ^ (c << 2))), wrow[32 + c], acc);
        acc = fmaf(x3v[n], wrow[64], acc);
        hconv[o * KTOP + k] = fmaxf(acc, 0.f);
    }
    __syncthreads();

    // maxpool(2,2): [16,20] -> [16,10]
    if (tid < 160) {
        int o = tid / 10, t = tid % 10;
        hp[o * 10 + t] = fmaxf(hconv[o * KTOP + 2 * t], hconv[o * KTOP + 2 * t + 1]);
    }
    __syncthreads();

    // conv2: Conv1d(16,32,5) valid -> [32,6], relu
    if (tid < 192) {
        int o = tid / 6, t = tid % 6;
        float acc = c2b[o];
        #pragma unroll
        for (int i2 = 0; i2 < 16; i2++)
            #pragma unroll
            for (int j = 0; j < 5; j++)
                acc = fmaf(hp[i2 * 10 + t + j], c2w[(o * 16 + i2) * 5 + j], acc);
        feat2[o * 6 + t] = fmaxf(acc, 0.f);
    }
    __syncthreads();

    // lin1: [192] @ [192,128] + b, relu
    if (tid < 128) {
        float acc = l1bg[tid];
        #pragma unroll 8
        for (int c = 0; c < 192; c++)
            acc = fmaf(feat2[c], l1wg[c * 128 + tid], acc);
        o1[tid] = fmaxf(acc, 0.f);
    }
    __syncthreads();

    // lin2: [128] @ [128,2] + b -> out[g,0..1]
    if (tid < 64) {
        int w = tid >> 5, l = tid & 31;
        float p = o1[l]        * l2wg[l * 2 + w]
                + o1[l + 32]   * l2wg[(l + 32) * 2 + w]
                + o1[l + 64]   * l2wg[(l + 64) * 2 + w]
                + o1[l + 96]   * l2wg[(l + 96) * 2 + w];
        #pragma unroll
        for (int off = 16; off; off >>= 1) p += __shfl_down_sync(0xffffffffu, p, off);
        if (l == 0) out[g * 2 + w] = p + l2bg[w];
    }
}

extern "C" void kernel_launch(void* const* d_in, const int* in_sizes, int n_in,
                              void* d_out, int out_size)
{
    const float* x    = (const float*)d_in[0];
    const int*   ei   = (const int*)d_in[1];
    // d_in[2] = batch (unused; graphs are contiguous)
    const float* W0   = (const float*)d_in[3];
    const float* b0   = (const float*)d_in[4];
    const float* W1   = (const float*)d_in[5];
    const float* b1   = (const float*)d_in[6];
    const float* W2   = (const float*)d_in[7];
    const float* b2   = (const float*)d_in[8];
    const float* c1w  = (const float*)d_in[9];
    const float* c1b  = (const float*)d_in[10];
    const float* c2w  = (const float*)d_in[11];
    const float* c2b  = (const float*)d_in[12];
    const float* l1w  = (const float*)d_in[13];
    const float* l1b  = (const float*)d_in[14];
    const float* l2w  = (const float*)d_in[15];
    const float* l2b  = (const float*)d_in[16];
    float* out = (float*)d_out;

    const long E = (long)in_sizes[1] / 2;   // 4,194,304
    const int* esrc = ei;
    const int* edst = ei + E;

    const size_t SMEM = 223248;
    cudaFuncSetAttribute(dgcnn_fused_kernel,
                         cudaFuncAttributeMaxDynamicSharedMemorySize, (int)SMEM);

    dgcnn_fused_kernel<<<NGRAPH, NT, SMEM>>>(
        x, esrc, edst, W0, b0, W1, b1, W2, b2,
        c1w, c1b, c2w, c2b, l1w, l1b, l2w, l2b, out);
}

// round 15
// speedup vs baseline: 1.1880x; 1.0065x over previous
#include <cuda_runtime.h>
#include <math.h>

#define NGRAPH 512
#define NPG    512      // nodes per graph
#define EPG    8192     // edges per graph
#define CIN    128
#define HID    32
#define KTOP   20
#define NT     1024     // threads per CTA (32 warps)

// monotonic float -> uint mapping (order-preserving)
__device__ __forceinline__ unsigned ordkey(float f) {
    unsigned u = __float_as_uint(f);
    return (u & 0x80000000u) ? ~u : (u | 0x80000000u);
}

// Accurate tanh that survives --use_fast_math
__device__ __forceinline__ float tanh_acc(float x) {
    float ax = fabsf(x);
    float e  = __expf(ax + ax);
    float r  = 1.0f - __fdividef(2.0f, e + 1.0f);
    return copysignf(r, x);
}

// packed f32x2 fma: d = a*b + d  (Blackwell FFMA2)
#define FFMA2(d, a, b) asm("fma.rn.f32x2 %0, %1, %2, %0;" : "+l"(d) : "l"(a), "l"(b))
// packed f32x2 add: a += v
#define ADDF2(a, v)    asm("add.rn.f32x2 %0, %0, %1;" : "+l"(a) : "l"(v))
__device__ __forceinline__ unsigned long long packdup(float v) {
    unsigned long long r;
    asm("mov.b64 %0, {%1, %1};" : "=l"(r) : "r"(__float_as_uint(v)));
    return r;
}

// swizzled row-base byte offset for node n. Row = 128B. Swizzle constant
// s = (n&30) ^ ((n&1)<<4) is EVEN (preserves channel-pair order for LDS.64)
// and distinct for 16 consecutive nodes (conflict-free epilogue writes).
__device__ __forceinline__ int swb(int n) {
    int s = (n & 30) ^ ((n & 1) << 4);
    return (n << 7) | (s << 2);
}

__global__ __launch_bounds__(NT, 1)
void dgcnn_fused_kernel(const float* __restrict__ x,
                        const int*   __restrict__ esrc,
                        const int*   __restrict__ edst,
                        const float* __restrict__ W0g, const float* __restrict__ b0g,
                        const float* __restrict__ W1g, const float* __restrict__ b1g,
                        const float* __restrict__ W2g, const float* __restrict__ b2g,
                        const float* __restrict__ c1wg, const float* __restrict__ c1bg,
                        const float* __restrict__ c2wg, const float* __restrict__ c2bg,
                        const float* __restrict__ l1wg, const float* __restrict__ l1bg,
                        const float* __restrict__ l2wg, const float* __restrict__ l2bg,
                        float* __restrict__ out)
{
    extern __shared__ char SM[];
    char*  Ac  = SM;                      // h (pre-scaled by dis), swizzled 512x32 f32
    char*  Bc  = SM + 65536;              // x staging (matmul1) then x1
    char*  Cc  = SM + 131072;             // x2
    float* dis = (float*)(SM + 196608);   // 512 f
    int*   indptr = (int*)(SM + 198656);  // 514 i32
    unsigned short* csr = (unsigned short*)(SM + 200712);  // 8192 u16
    float* x3v = (float*)(SM + 217096);   // 512 f
    char*  U   = SM + 219152;             // 4096 B scratch, 16B-aligned

    const int tid  = threadIdx.x;
    const int lane = tid & 31;
    const int wid  = tid >> 5;          // 0..31
    const int g    = blockIdx.x;
    const int nbase = g * NPG;
    const long ebase = (long)g * EPG;

    // gather constants: half-warp-per-edge scheme
    const int hl   = lane & 15;         // channel-pair index (2 ch / lane)
    const int half = lane >> 4;         // 0: even edge, 1: odd edge
    const unsigned u8 = (unsigned)hl << 3;               // 8B unit offset
    const unsigned psel = half ? 0x4432u : 0x4410u;      // PRMT: extract u16

    // ================= degree count =================
    if (tid < 514) indptr[tid] = 0;
    __syncthreads();

    #pragma unroll
    for (int i = 0; i < EPG / NT; i++) {
        int e = tid + i * NT;
        int d = edst[ebase + e] - nbase;
        atomicAdd(&indptr[d + 1], 1);
    }
    __syncthreads();

    // dis = rsqrt(deg + 1)
    if (tid < 512) dis[tid] = rsqrtf((float)indptr[tid + 1] + 1.0f);

    // ================= exclusive scan -> indptr (512 values) =================
    {
        int v = (tid < 512) ? indptr[tid + 1] : 0;
        #pragma unroll
        for (int off = 1; off < 32; off <<= 1) {
            int n = __shfl_up_sync(0xffffffffu, v, off);
            if (lane >= off) v += n;
        }
        int* wsum = (int*)U;
        if (lane == 31 && wid < 16) wsum[wid] = v;
        __syncthreads();
        if (wid == 0) {
            int s = (lane < 16) ? wsum[lane] : 0;
            #pragma unroll
            for (int off = 1; off < 16; off <<= 1) {
                int n = __shfl_up_sync(0xffffffffu, s, off);
                if (lane >= off) s += n;
            }
            if (lane < 16) wsum[lane] = s;
        }
        __syncthreads();
        int incl = 0;
        if (tid < 512) {
            int prefix = (wid > 0) ? wsum[wid - 1] : 0;
            incl = v + prefix;
        }
        __syncthreads();            // everyone done reading wsum
        if (tid < 512) indptr[tid + 1] = incl;
        if (tid == 0) indptr[0] = 0;
        __syncthreads();
    }

    // ================= CSR fill (entries are pre-swizzled byte offsets) ======
    {
        int* pos = (int*)U;
        if (tid < 512) pos[tid] = indptr[tid];
        __syncthreads();
        #pragma unroll
        for (int i = 0; i < EPG / NT; i++) {
            int e = tid + i * NT;
            int s = esrc[ebase + e] - nbase;
            int d = edst[ebase + e] - nbase;
            int p = atomicAdd(&pos[d], 1);
            csr[p] = (unsigned short)swb(s);
        }
    }
    // sync at top of matmul1 chunk loop

    const int node = tid >> 1;          // matmul: pair-split over channels
    const int mhalf = tid & 1;          // 0: ch 0-15, 1: ch 16-31
    const int vnode = swb(node);

    // ================= Layer 1 matmul: A = (x_g @ W0) * dis =================
    {
        unsigned long long acc2[8];
        #pragma unroll
        for (int j = 0; j < 8; j++) acc2[j] = 0ull;
        float* Wc = (float*)U;
        const float* xg = x + (size_t)nbase * CIN;
        const unsigned ul = (unsigned)lane * 2052u;   // ch*2048 + ch*4
        for (int cb = 0; cb < 4; cb++) {
            __syncthreads();
            // stage x chunk transposed into B: row=channel (2048B stride, XOR swizzle)
            #pragma unroll
            for (int i = 0; i < 16; i++) {
                int n = i * 32 + wid;
                *(float*)(Bc + (ul ^ (unsigned)(n << 2))) = xg[(size_t)n * CIN + cb * 32 + lane];
            }
            Wc[tid] = W0g[cb * 1024 + tid];
            __syncthreads();
            const ulonglong2* W2p = (const ulonglong2*)Wc;
            #pragma unroll 4
            for (int c = 0; c < 32; c++) {
                unsigned long long xx = packdup(*(const float*)(Bc + ((c * 2052) ^ (node << 2))));
                #pragma unroll
                for (int o4 = 0; o4 < 4; o4++) {
                    ulonglong2 wv = W2p[c * 8 + mhalf * 4 + o4];
                    FFMA2(acc2[o4 * 2 + 0], xx, wv.x);
                    FFMA2(acc2[o4 * 2 + 1], xx, wv.y);
                }
            }
        }
        float dn = dis[node];
        int cbase = mhalf << 4;
        #pragma unroll
        for (int o4 = 0; o4 < 4; o4++) {
            float2 f0 = *reinterpret_cast<float2*>(&acc2[o4 * 2 + 0]);
            float2 f1 = *reinterpret_cast<float2*>(&acc2[o4 * 2 + 1]);
            *(float*)(Ac + (vnode ^ ((cbase + o4 * 4 + 0) << 2))) = f0.x * dn;
            *(float*)(Ac + (vnode ^ ((cbase + o4 * 4 + 1) << 2))) = f0.y * dn;
            *(float*)(Ac + (vnode ^ ((cbase + o4 * 4 + 2) << 2))) = f1.x * dn;
            *(float*)(Ac + (vnode ^ ((cbase + o4 * 4 + 3) << 2))) = f1.y * dn;
        }
    }
    __syncthreads();

    // ================= Layer 1 gather -> x1 in B (8-edge blocks, MLP=4) =====
    {
        float bla = b0g[2 * hl], blb = b0g[2 * hl + 1];
        for (int n = wid; n < NPG; n += 32) {
            int vn = swb(n);
            unsigned long long acc = 0ull;
            if (!half) acc = *(const unsigned long long*)(Ac + ((unsigned)vn ^ u8));  // self
            int e = indptr[n], end = indptr[n + 1];
            if (e < end && (e & 1)) {                     // peel to even e
                if (!half) {
                    unsigned long long v = *(const unsigned long long*)(Ac + ((unsigned)csr[e] ^ u8));
                    ADDF2(acc, v);
                }
                e++;
            }
            // 8-edge blocks: 4 csr words batched (MLP 4), 4 value loads (MLP 4)
            for (; e + 7 < end; e += 8) {
                unsigned w0 = *(const unsigned*)(csr + e);
                unsigned w1 = *(const unsigned*)(csr + e + 2);
                unsigned w2 = *(const unsigned*)(csr + e + 4);
                unsigned w3 = *(const unsigned*)(csr + e + 6);
                unsigned vo0 = __byte_perm(w0, 0, psel);
                unsigned vo1 = __byte_perm(w1, 0, psel);
                unsigned vo2 = __byte_perm(w2, 0, psel);
                unsigned vo3 = __byte_perm(w3, 0, psel);
                unsigned long long v0 = *(const unsigned long long*)(Ac + (vo0 ^ u8));
                unsigned long long v1 = *(const unsigned long long*)(Ac + (vo1 ^ u8));
                unsigned long long v2 = *(const unsigned long long*)(Ac + (vo2 ^ u8));
                unsigned long long v3 = *(const unsigned long long*)(Ac + (vo3 ^ u8));
                ADDF2(acc, v0);
                ADDF2(acc, v1);
                ADDF2(acc, v2);
                ADDF2(acc, v3);
            }
            for (; e + 3 < end; e += 4) {
                unsigned w0 = *(const unsigned*)(csr + e);
                unsigned w1 = *(const unsigned*)(csr + e + 2);
                unsigned vo0 = __byte_perm(w0, 0, psel);
                unsigned vo1 = __byte_perm(w1, 0, psel);
                unsigned long long v0 = *(const unsigned long long*)(Ac + (vo0 ^ u8));
                unsigned long long v1 = *(const unsigned long long*)(Ac + (vo1 ^ u8));
                ADDF2(acc, v0);
                ADDF2(acc, v1);
            }
            if (e + 1 < end) {
                unsigned w0 = *(const unsigned*)(csr + e);
                unsigned vo0 = __byte_perm(w0, 0, psel);
                unsigned long long v0 = *(const unsigned long long*)(Ac + (vo0 ^ u8));
                ADDF2(acc, v0);
                e += 2;
            }
            if (e < end && !half) {                       // tail single edge
                unsigned long long v = *(const unsigned long long*)(Ac + ((unsigned)csr[e] ^ u8));
                ADDF2(acc, v);
            }
            // merge halves
            float ax = __uint_as_float((unsigned)acc);
            float ay = __uint_as_float((unsigned)(acc >> 32));
            ax += __shfl_xor_sync(0xffffffffu, ax, 16);
            ay += __shfl_xor_sync(0xffffffffu, ay, 16);
            if (!half) {
                float dn = dis[n];
                float2 r;
                r.x = tanh_acc(fmaf(ax, dn, bla));
                r.y = tanh_acc(fmaf(ay, dn, blb));
                *(float2*)(Bc + ((unsigned)vn ^ u8)) = r;
            }
        }
    }
    __syncthreads();

    // ================= Layer 2 matmul: A = (x1 @ W1) * dis =================
    {
        float* Wc = (float*)U;
        Wc[tid] = W1g[tid];
        __syncthreads();
        unsigned long long acc2[8];
        #pragma unroll
        for (int j = 0; j < 8; j++) acc2[j] = 0ull;
        const ulonglong2* W2p = (const ulonglong2*)Wc;
        #pragma unroll 4
        for (int c = 0; c < 32; c++) {
            unsigned long long xx = packdup(*(const float*)(Bc + (vnode ^ (c << 2))));
            #pragma unroll
            for (int o4 = 0; o4 < 4; o4++) {
                ulonglong2 wv = W2p[c * 8 + mhalf * 4 + o4];
                FFMA2(acc2[o4 * 2 + 0], xx, wv.x);
                FFMA2(acc2[o4 * 2 + 1], xx, wv.y);
            }
        }
        __syncthreads();   // Wc (U) reused later; also order vs next stage
        float dn = dis[node];
        int cbase = mhalf << 4;
        #pragma unroll
        for (int o4 = 0; o4 < 4; o4++) {
            float2 f0 = *reinterpret_cast<float2*>(&acc2[o4 * 2 + 0]);
            float2 f1 = *reinterpret_cast<float2*>(&acc2[o4 * 2 + 1]);
            *(float*)(Ac + (vnode ^ ((cbase + o4 * 4 + 0) << 2))) = f0.x * dn;
            *(float*)(Ac + (vnode ^ ((cbase + o4 * 4 + 1) << 2))) = f0.y * dn;
            *(float*)(Ac + (vnode ^ ((cbase + o4 * 4 + 2) << 2))) = f1.x * dn;
            *(float*)(Ac + (vnode ^ ((cbase + o4 * 4 + 3) << 2))) = f1.y * dn;
        }
    }
    __syncthreads();

    // ================= Layer 2 gather -> x2 in C (8-edge blocks, MLP=4) =====
    {
        float bla = b1g[2 * hl], blb = b1g[2 * hl + 1];
        for (int n = wid; n < NPG; n += 32) {
            int vn = swb(n);
            unsigned long long acc = 0ull;
            if (!half) acc = *(const unsigned long long*)(Ac + ((unsigned)vn ^ u8));
            int e = indptr[n], end = indptr[n + 1];
            if (e < end && (e & 1)) {
                if (!half) {
                    unsigned long long v = *(const unsigned long long*)(Ac + ((unsigned)csr[e] ^ u8));
                    ADDF2(acc, v);
                }
                e++;
            }
            for (; e + 7 < end; e += 8) {
                unsigned w0 = *(const unsigned*)(csr + e);
                unsigned w1 = *(const unsigned*)(csr + e + 2);
                unsigned w2 = *(const unsigned*)(csr + e + 4);
                unsigned w3 = *(const unsigned*)(csr + e + 6);
                unsigned vo0 = __byte_perm(w0, 0, psel);
                unsigned vo1 = __byte_perm(w1, 0, psel);
                unsigned vo2 = __byte_perm(w2, 0, psel);
                unsigned vo3 = __byte_perm(w3, 0, psel);
                unsigned long long v0 = *(const unsigned long long*)(Ac + (vo0 ^ u8));
                unsigned long long v1 = *(const unsigned long long*)(Ac + (vo1 ^ u8));
                unsigned long long v2 = *(const unsigned long long*)(Ac + (vo2 ^ u8));
                unsigned long long v3 = *(const unsigned long long*)(Ac + (vo3 ^ u8));
                ADDF2(acc, v0);
                ADDF2(acc, v1);
                ADDF2(acc, v2);
                ADDF2(acc, v3);
            }
            for (; e + 3 < end; e += 4) {
                unsigned w0 = *(const unsigned*)(csr + e);
                unsigned w1 = *(const unsigned*)(csr + e + 2);
                unsigned vo0 = __byte_perm(w0, 0, psel);
                unsigned vo1 = __byte_perm(w1, 0, psel);
                unsigned long long v0 = *(const unsigned long long*)(Ac + (vo0 ^ u8));
                unsigned long long v1 = *(const unsigned long long*)(Ac + (vo1 ^ u8));
                ADDF2(acc, v0);
                ADDF2(acc, v1);
            }
            if (e + 1 < end) {
                unsigned w0 = *(const unsigned*)(csr + e);
                unsigned vo0 = __byte_perm(w0, 0, psel);
                unsigned long long v0 = *(const unsigned long long*)(Ac + (vo0 ^ u8));
                ADDF2(acc, v0);
                e += 2;
            }
            if (e < end && !half) {
                unsigned long long v = *(const unsigned long long*)(Ac + ((unsigned)csr[e] ^ u8));
                ADDF2(acc, v);
            }
            float ax = __uint_as_float((unsigned)acc);
            float ay = __uint_as_float((unsigned)(acc >> 32));
            ax += __shfl_xor_sync(0xffffffffu, ax, 16);
            ay += __shfl_xor_sync(0xffffffffu, ay, 16);
            if (!half) {
                float dn = dis[n];
                float2 r;
                r.x = tanh_acc(fmaf(ax, dn, bla));
                r.y = tanh_acc(fmaf(ay, dn, blb));
                *(float2*)(Cc + ((unsigned)vn ^ u8)) = r;
            }
        }
    }
    __syncthreads();

    // ================= Layer 3: h2' = (x2 @ W2)*dis, gather -> x3v ==========
    {
        float w2l = W2g[lane];
        float* h2 = (float*)U;
        for (int n = wid; n < NPG; n += 32) {
            float v = *(const float*)(Cc + (swb(n) ^ (lane << 2))) * w2l;
            #pragma unroll
            for (int off = 16; off; off >>= 1) v += __shfl_down_sync(0xffffffffu, v, off);
            if (lane == 0) h2[n] = v * dis[n];   // pre-scaled
        }
    }
    __syncthreads();
    {
        float* h2 = (float*)U;
        float b2 = b2g[0];
        for (int n = wid; n < NPG; n += 32) {
            int beg = indptr[n], end = indptr[n + 1];
            float p = 0.f;
            for (int e = beg + lane; e < end; e += 32)
                p += h2[csr[e] >> 7];            // recover node id from offset
            #pragma unroll
            for (int off = 16; off; off >>= 1) p += __shfl_down_sync(0xffffffffu, p, off);
            if (lane == 0) {
                float tot = p + h2[n];
                x3v[n] = tanh_acc(fmaf(tot, dis[n], b2));
            }
        }
    }
    __syncthreads();

    // ================= stable top-K: bitonic sort of 512 keys ===============
    unsigned long long* keys = (unsigned long long*)U;
    if (tid < 512)
        keys[tid] = ((unsigned long long)ordkey(x3v[tid]) << 32)
                  | (unsigned long long)(0xFFFFFFFFu - (unsigned)tid);
    __syncthreads();
    for (int k = 2; k <= 512; k <<= 1) {
        for (int j = k >> 1; j > 0; j >>= 1) {
            if (tid < 512) {
                int ixj = tid ^ j;
                if (ixj > tid) {
                    unsigned long long a = keys[tid], b = keys[ixj];
                    bool desc = ((tid & k) == 0);
                    if (desc ? (a < b) : (a > b)) { keys[tid] = b; keys[ixj] = a; }
                }
            }
            __syncthreads();
        }
    }

    // ================= tail: conv1 -> maxpool -> conv2 -> lin1 -> lin2 ======
    float* hconv = (float*)Ac;        // 320
    float* hp    = (float*)Ac + 320;  // 160
    float* feat2 = (float*)Ac + 480;  // 192
    float* o1    = (float*)Ac + 672;  // 128
    int*   topn  = (int*)((float*)Ac + 800);  // 20
    float* WS  = (float*)csr;   // CSR dead; 16 KB scratch
    float* c1w = WS;            // 1040
    float* c1b = WS + 1040;     // 16
    float* c2w = WS + 1056;     // 2560
    float* c2b = WS + 3616;     // 32

    for (int i = tid; i < 1040; i += NT) c1w[i] = c1wg[i];
    if (tid < 16) c1b[tid] = c1bg[tid];
    for (int i = tid; i < 2560; i += NT) c2w[i] = c2wg[i];
    if (tid < 32) c2b[tid] = c2bg[tid];
    if (tid < KTOP) topn[tid] = (int)(0xFFFFFFFFu - (unsigned)(keys[tid] & 0xFFFFFFFFull));
    __syncthreads();

    // conv1: [16,K] = relu(pooled . w + b)
    if (tid < 16 * KTOP) {
        int o = tid & 15, k = tid >> 4;
        int n = topn[k];
        int vn = swb(n);
        float acc = c1b[o];
        const float* wrow = c1w + o * 65;
        #pragma unroll
        for (int c = 0; c < 32; c++)
            acc = fmaf(*(const float*)(Bc + (vn ^ (c << 2))), wrow[c], acc);
        #pragma unroll
        for (int c = 0; c < 32; c++)
            acc = fmaf(*(const float*)(Cc + (vn ^ (c << 2))), wrow[32 + c], acc);
        acc = fmaf(x3v[n], wrow[64], acc);
        hconv[o * KTOP + k] = fmaxf(acc, 0.f);
    }
    __syncthreads();

    // maxpool(2,2): [16,20] -> [16,10]
    if (tid < 160) {
        int o = tid / 10, t = tid % 10;
        hp[o * 10 + t] = fmaxf(hconv[o * KTOP + 2 * t], hconv[o * KTOP + 2 * t + 1]);
    }
    __syncthreads();

    // conv2: Conv1d(16,32,5) valid -> [32,6], relu
    if (tid < 192) {
        int o = tid / 6, t = tid % 6;
        float acc = c2b[o];
        #pragma unroll
        for (int i2 = 0; i2 < 16; i2++)
            #pragma unroll
            for (int j = 0; j < 5; j++)
                acc = fmaf(hp[i2 * 10 + t + j], c2w[(o * 16 + i2) * 5 + j], acc);
        feat2[o * 6 + t] = fmaxf(acc, 0.f);
    }
    __syncthreads();

    // lin1: [192] @ [192,128] + b, relu
    if (tid < 128) {
        float acc = l1bg[tid];
        #pragma unroll 8
        for (int c = 0; c < 192; c++)
            acc = fmaf(feat2[c], l1wg[c * 128 + tid], acc);
        o1[tid] = fmaxf(acc, 0.f);
    }
    __syncthreads();

    // lin2: [128] @ [128,2] + b -> out[g,0..1]
    if (tid < 64) {
        int w = tid >> 5, l = tid & 31;
        float p = o1[l]        * l2wg[l * 2 + w]
                + o1[l + 32]   * l2wg[(l + 32) * 2 + w]
                + o1[l + 64]   * l2wg[(l + 64) * 2 + w]
                + o1[l + 96]   * l2wg[(l + 96) * 2 + w];
        #pragma unroll
        for (int off = 16; off; off >>= 1) p += __shfl_down_sync(0xffffffffu, p, off);
        if (l == 0) out[g * 2 + w] = p + l2bg[w];
    }
}

extern "C" void kernel_launch(void* const* d_in, const int* in_sizes, int n_in,
                              void* d_out, int out_size)
{
    const float* x    = (const float*)d_in[0];
    const int*   ei   = (const int*)d_in[1];
    // d_in[2] = batch (unused; graphs are contiguous)
    const float* W0   = (const float*)d_in[3];
    const float* b0   = (const float*)d_in[4];
    const float* W1   = (const float*)d_in[5];
    const float* b1   = (const float*)d_in[6];
    const float* W2   = (const float*)d_in[7];
    const float* b2   = (const float*)d_in[8];
    const float* c1w  = (const float*)d_in[9];
    const float* c1b  = (const float*)d_in[10];
    const float* c2w  = (const float*)d_in[11];
    const float* c2b  = (const float*)d_in[12];
    const float* l1w  = (const float*)d_in[13];
    const float* l1b  = (const float*)d_in[14];
    const float* l2w  = (const float*)d_in[15];
    const float* l2b  = (const float*)d_in[16];
    float* out = (float*)d_out;

    const long E = (long)in_sizes[1] / 2;   // 4,194,304
    const int* esrc = ei;
    const int* edst = ei + E;

    const size_t SMEM = 223248;
    cudaFuncSetAttribute(dgcnn_fused_kernel,
                         cudaFuncAttributeMaxDynamicSharedMemorySize, (int)SMEM);

    dgcnn_fused_kernel<<<NGRAPH, NT, SMEM>>>(
        x, esrc, edst, W0, b0, W1, b1, W2, b2,
        c1w, c1b, c2w, c2b, l1w, l1b, l2w, l2b, out);
}

// round 17
// speedup vs baseline: 1.2021x; 1.0119x over previous
#include <cuda_runtime.h>
#include <math.h>

#define NGRAPH 512
#define NPG    512      // nodes per graph
#define EPG    8192     // edges per graph
#define CIN    128
#define HID    32
#define KTOP   20
#define NT     1024     // threads per CTA (32 warps)

// monotonic float -> uint mapping (order-preserving)
__device__ __forceinline__ unsigned ordkey(float f) {
    unsigned u = __float_as_uint(f);
    return (u & 0x80000000u) ? ~u : (u | 0x80000000u);
}

// Accurate tanh that survives --use_fast_math
__device__ __forceinline__ float tanh_acc(float x) {
    float ax = fabsf(x);
    float e  = __expf(ax + ax);
    float r  = 1.0f - __fdividef(2.0f, e + 1.0f);
    return copysignf(r, x);
}

// packed f32x2 fma: d = a*b + d  (Blackwell FFMA2)
#define FFMA2(d, a, b) asm("fma.rn.f32x2 %0, %1, %2, %0;" : "+l"(d) : "l"(a), "l"(b))
// packed f32x2 add: a += v
#define ADDF2(a, v)    asm("add.rn.f32x2 %0, %0, %1;" : "+l"(a) : "l"(v))
__device__ __forceinline__ unsigned long long packdup(float v) {
    unsigned long long r;
    asm("mov.b64 %0, {%1, %1};" : "=l"(r) : "r"(__float_as_uint(v)));
    return r;
}

// swizzled row-base byte offset for node n. Row = 128B. Swizzle constant
// s = (n&30) ^ ((n&1)<<4) is EVEN (preserves channel-pair order for LDS.64)
// and distinct for 16 consecutive nodes (conflict-free epilogue writes).
__device__ __forceinline__ int swb(int n) {
    int s = (n & 30) ^ ((n & 1) << 4);
    return (n << 7) | (s << 2);
}

__global__ __launch_bounds__(NT, 1)
void dgcnn_fused_kernel(const float* __restrict__ x,
                        const int*   __restrict__ esrc,
                        const int*   __restrict__ edst,
                        const float* __restrict__ W0g, const float* __restrict__ b0g,
                        const float* __restrict__ W1g, const float* __restrict__ b1g,
                        const float* __restrict__ W2g, const float* __restrict__ b2g,
                        const float* __restrict__ c1wg, const float* __restrict__ c1bg,
                        const float* __restrict__ c2wg, const float* __restrict__ c2bg,
                        const float* __restrict__ l1wg, const float* __restrict__ l1bg,
                        const float* __restrict__ l2wg, const float* __restrict__ l2bg,
                        float* __restrict__ out)
{
    extern __shared__ char SM[];
    char*  Ac  = SM;                      // h (pre-scaled by dis), swizzled 512x32 f32
    char*  Bc  = SM + 65536;              // x1
    char*  Cc  = SM + 131072;             // W0 stage (matmul1) then x2
    float* dis = (float*)(SM + 196608);   // 512 f
    int*   indptr = (int*)(SM + 198656);  // 514 i32
    unsigned short* csr = (unsigned short*)(SM + 200712);  // 8192 u16
    float* x3v = (float*)(SM + 217096);   // 512 f
    char*  U   = SM + 219152;             // 4096 B scratch, 16B-aligned

    const int tid  = threadIdx.x;
    const int lane = tid & 31;
    const int wid  = tid >> 5;          // 0..31
    const int g    = blockIdx.x;
    const int nbase = g * NPG;
    const long ebase = (long)g * EPG;

    // gather constants: half-warp-per-edge scheme
    const int hl   = lane & 15;         // channel-pair index (2 ch / lane)
    const int half = lane >> 4;         // 0: even edge, 1: odd edge
    const unsigned u8 = (unsigned)hl << 3;               // 8B unit offset
    const unsigned psel = half ? 0x4432u : 0x4410u;      // PRMT: extract u16

    // ================= degree count (+ W0 full stage into Cc) ==============
    if (tid < 514) indptr[tid] = 0;
    // stage W0 (128x32 f32 = 16KB) into Cc once; used by matmul1
    {
        float* Wf = (float*)Cc;
        #pragma unroll
        for (int i = 0; i < 4; i++) Wf[tid + i * NT] = W0g[tid + i * NT];
    }
    __syncthreads();

    #pragma unroll
    for (int i = 0; i < EPG / NT; i++) {
        int e = tid + i * NT;
        int d = edst[ebase + e] - nbase;
        atomicAdd(&indptr[d + 1], 1);
    }
    __syncthreads();

    // dis = rsqrt(deg + 1)
    if (tid < 512) dis[tid] = rsqrtf((float)indptr[tid + 1] + 1.0f);

    // ================= exclusive scan -> indptr (512 values) =================
    {
        int v = (tid < 512) ? indptr[tid + 1] : 0;
        #pragma unroll
        for (int off = 1; off < 32; off <<= 1) {
            int n = __shfl_up_sync(0xffffffffu, v, off);
            if (lane >= off) v += n;
        }
        int* wsum = (int*)U;
        if (lane == 31 && wid < 16) wsum[wid] = v;
        __syncthreads();
        if (wid == 0) {
            int s = (lane < 16) ? wsum[lane] : 0;
            #pragma unroll
            for (int off = 1; off < 16; off <<= 1) {
                int n = __shfl_up_sync(0xffffffffu, s, off);
                if (lane >= off) s += n;
            }
            if (lane < 16) wsum[lane] = s;
        }
        __syncthreads();
        int incl = 0;
        if (tid < 512) {
            int prefix = (wid > 0) ? wsum[wid - 1] : 0;
            incl = v + prefix;
        }
        __syncthreads();            // everyone done reading wsum
        if (tid < 512) indptr[tid + 1] = incl;
        if (tid == 0) indptr[0] = 0;
        __syncthreads();
    }

    // ================= CSR fill (entries are pre-swizzled byte offsets) ======
    {
        int* pos = (int*)U;
        if (tid < 512) pos[tid] = indptr[tid];
        __syncthreads();
        #pragma unroll
        for (int i = 0; i < EPG / NT; i++) {
            int e = tid + i * NT;
            int s = esrc[ebase + e] - nbase;
            int d = edst[ebase + e] - nbase;
            int p = atomicAdd(&pos[d], 1);
            csr[p] = (unsigned short)swb(s);
        }
    }
    __syncthreads();   // csr + W0 stage complete

    const int node = tid >> 1;          // matmul: pair-split over channels
    const int mhalf = tid & 1;          // 0: ch 0-15, 1: ch 16-31
    const int vnode = swb(node);

    // ================= Layer 1 matmul: A = (x_g @ W0) * dis ================
    // x read directly from GMEM (float4), W0 from Cc stage. No staging barriers.
    {
        unsigned long long acc2[8];
        #pragma unroll
        for (int j = 0; j < 8; j++) acc2[j] = 0ull;
        const float4* xg4 = (const float4*)(x + (size_t)(nbase + node) * CIN);
        const ulonglong2* Wq = (const ulonglong2*)Cc;
        #pragma unroll 4
        for (int k4 = 0; k4 < 32; k4++) {
            float4 xv = xg4[k4];
            unsigned long long xx0 = packdup(xv.x);
            unsigned long long xx1 = packdup(xv.y);
            unsigned long long xx2 = packdup(xv.z);
            unsigned long long xx3 = packdup(xv.w);
            int kb = k4 * 32 + mhalf * 4;      // ulonglong2 index of row k4*4, this half
            #pragma unroll
            for (int o4 = 0; o4 < 4; o4++) {
                ulonglong2 w0 = Wq[kb + o4];
                ulonglong2 w1 = Wq[kb + 8 + o4];
                ulonglong2 w2 = Wq[kb + 16 + o4];
                ulonglong2 w3 = Wq[kb + 24 + o4];
                FFMA2(acc2[o4 * 2 + 0], xx0, w0.x);
                FFMA2(acc2[o4 * 2 + 1], xx0, w0.y);
                FFMA2(acc2[o4 * 2 + 0], xx1, w1.x);
                FFMA2(acc2[o4 * 2 + 1], xx1, w1.y);
                FFMA2(acc2[o4 * 2 + 0], xx2, w2.x);
                FFMA2(acc2[o4 * 2 + 1], xx2, w2.y);
                FFMA2(acc2[o4 * 2 + 0], xx3, w3.x);
                FFMA2(acc2[o4 * 2 + 1], xx3, w3.y);
            }
        }
        float dn = dis[node];
        int cbase = mhalf << 4;
        #pragma unroll
        for (int o4 = 0; o4 < 4; o4++) {
            float2 f0 = *reinterpret_cast<float2*>(&acc2[o4 * 2 + 0]);
            float2 f1 = *reinterpret_cast<float2*>(&acc2[o4 * 2 + 1]);
            *(float*)(Ac + (vnode ^ ((cbase + o4 * 4 + 0) << 2))) = f0.x * dn;
            *(float*)(Ac + (vnode ^ ((cbase + o4 * 4 + 1) << 2))) = f0.y * dn;
            *(float*)(Ac + (vnode ^ ((cbase + o4 * 4 + 2) << 2))) = f1.x * dn;
            *(float*)(Ac + (vnode ^ ((cbase + o4 * 4 + 3) << 2))) = f1.y * dn;
        }
    }
    __syncthreads();

    // ================= Layer 1 gather -> x1 in B (8-edge blocks, MLP=4) =====
    {
        float bla = b0g[2 * hl], blb = b0g[2 * hl + 1];
        for (int n = wid; n < NPG; n += 32) {
            int vn = swb(n);
            unsigned long long acc = 0ull;
            if (!half) acc = *(const unsigned long long*)(Ac + ((unsigned)vn ^ u8));  // self
            int e = indptr[n], end = indptr[n + 1];
            if (e < end && (e & 1)) {                     // peel to even e
                if (!half) {
                    unsigned long long v = *(const unsigned long long*)(Ac + ((unsigned)csr[e] ^ u8));
                    ADDF2(acc, v);
                }
                e++;
            }
            // 8-edge blocks: 4 csr words batched (MLP 4), 4 value loads (MLP 4)
            for (; e + 7 < end; e += 8) {
                unsigned w0 = *(const unsigned*)(csr + e);
                unsigned w1 = *(const unsigned*)(csr + e + 2);
                unsigned w2 = *(const unsigned*)(csr + e + 4);
                unsigned w3 = *(const unsigned*)(csr + e + 6);
                unsigned vo0 = __byte_perm(w0, 0, psel);
                unsigned vo1 = __byte_perm(w1, 0, psel);
                unsigned vo2 = __byte_perm(w2, 0, psel);
                unsigned vo3 = __byte_perm(w3, 0, psel);
                unsigned long long v0 = *(const unsigned long long*)(Ac + (vo0 ^ u8));
                unsigned long long v1 = *(const unsigned long long*)(Ac + (vo1 ^ u8));
                unsigned long long v2 = *(const unsigned long long*)(Ac + (vo2 ^ u8));
                unsigned long long v3 = *(const unsigned long long*)(Ac + (vo3 ^ u8));
                ADDF2(acc, v0);
                ADDF2(acc, v1);
                ADDF2(acc, v2);
                ADDF2(acc, v3);
            }
            for (; e + 3 < end; e += 4) {
                unsigned w0 = *(const unsigned*)(csr + e);
                unsigned w1 = *(const unsigned*)(csr + e + 2);
                unsigned vo0 = __byte_perm(w0, 0, psel);
                unsigned vo1 = __byte_perm(w1, 0, psel);
                unsigned long long v0 = *(const unsigned long long*)(Ac + (vo0 ^ u8));
                unsigned long long v1 = *(const unsigned long long*)(Ac + (vo1 ^ u8));
                ADDF2(acc, v0);
                ADDF2(acc, v1);
            }
            if (e + 1 < end) {
                unsigned w0 = *(const unsigned*)(csr + e);
                unsigned vo0 = __byte_perm(w0, 0, psel);
                unsigned long long v0 = *(const unsigned long long*)(Ac + (vo0 ^ u8));
                ADDF2(acc, v0);
                e += 2;
            }
            if (e < end && !half) {                       // tail single edge
                unsigned long long v = *(const unsigned long long*)(Ac + ((unsigned)csr[e] ^ u8));
                ADDF2(acc, v);
            }
            // merge halves
            float ax = __uint_as_float((unsigned)acc);
            float ay = __uint_as_float((unsigned)(acc >> 32));
            ax += __shfl_xor_sync(0xffffffffu, ax, 16);
            ay += __shfl_xor_sync(0xffffffffu, ay, 16);
            if (!half) {
                float dn = dis[n];
                float2 r;
                r.x = tanh_acc(fmaf(ax, dn, bla));
                r.y = tanh_acc(fmaf(ay, dn, blb));
                *(float2*)(Bc + ((unsigned)vn ^ u8)) = r;
            }
        }
    }
    __syncthreads();

    // ================= Layer 2 matmul: A = (x1 @ W1) * dis =================
    {
        float* Wc = (float*)U;
        Wc[tid] = W1g[tid];
        __syncthreads();
        unsigned long long acc2[8];
        #pragma unroll
        for (int j = 0; j < 8; j++) acc2[j] = 0ull;
        const ulonglong2* W2p = (const ulonglong2*)Wc;
        #pragma unroll 4
        for (int c = 0; c < 32; c++) {
            unsigned long long xx = packdup(*(const float*)(Bc + (vnode ^ (c << 2))));
            #pragma unroll
            for (int o4 = 0; o4 < 4; o4++) {
                ulonglong2 wv = W2p[c * 8 + mhalf * 4 + o4];
                FFMA2(acc2[o4 * 2 + 0], xx, wv.x);
                FFMA2(acc2[o4 * 2 + 1], xx, wv.y);
            }
        }
        __syncthreads();   // Wc (U) reused later; also order vs next stage
        float dn = dis[node];
        int cbase = mhalf << 4;
        #pragma unroll
        for (int o4 = 0; o4 < 4; o4++) {
            float2 f0 = *reinterpret_cast<float2*>(&acc2[o4 * 2 + 0]);
            float2 f1 = *reinterpret_cast<float2*>(&acc2[o4 * 2 + 1]);
            *(float*)(Ac + (vnode ^ ((cbase + o4 * 4 + 0) << 2))) = f0.x * dn;
            *(float*)(Ac + (vnode ^ ((cbase + o4 * 4 + 1) << 2))) = f0.y * dn;
            *(float*)(Ac + (vnode ^ ((cbase + o4 * 4 + 2) << 2))) = f1.x * dn;
            *(float*)(Ac + (vnode ^ ((cbase + o4 * 4 + 3) << 2))) = f1.y * dn;
        }
    }
    __syncthreads();

    // ================= Layer 2 gather -> x2 in C (8-edge blocks, MLP=4) =====
    {
        float bla = b1g[2 * hl], blb = b1g[2 * hl + 1];
        for (int n = wid; n < NPG; n += 32) {
            int vn = swb(n);
            unsigned long long acc = 0ull;
            if (!half) acc = *(const unsigned long long*)(Ac + ((unsigned)vn ^ u8));
            int e = indptr[n], end = indptr[n + 1];
            if (e < end && (e & 1)) {
                if (!half) {
                    unsigned long long v = *(const unsigned long long*)(Ac + ((unsigned)csr[e] ^ u8));
                    ADDF2(acc, v);
                }
                e++;
            }
            for (; e + 7 < end; e += 8) {
                unsigned w0 = *(const unsigned*)(csr + e);
                unsigned w1 = *(const unsigned*)(csr + e + 2);
                unsigned w2 = *(const unsigned*)(csr + e + 4);
                unsigned w3 = *(const unsigned*)(csr + e + 6);
                unsigned vo0 = __byte_perm(w0, 0, psel);
                unsigned vo1 = __byte_perm(w1, 0, psel);
                unsigned vo2 = __byte_perm(w2, 0, psel);
                unsigned vo3 = __byte_perm(w3, 0, psel);
                unsigned long long v0 = *(const unsigned long long*)(Ac + (vo0 ^ u8));
                unsigned long long v1 = *(const unsigned long long*)(Ac + (vo1 ^ u8));
                unsigned long long v2 = *(const unsigned long long*)(Ac + (vo2 ^ u8));
                unsigned long long v3 = *(const unsigned long long*)(Ac + (vo3 ^ u8));
                ADDF2(acc, v0);
                ADDF2(acc, v1);
                ADDF2(acc, v2);
                ADDF2(acc, v3);
            }
            for (; e + 3 < end; e += 4) {
                unsigned w0 = *(const unsigned*)(csr + e);
                unsigned w1 = *(const unsigned*)(csr + e + 2);
                unsigned vo0 = __byte_perm(w0, 0, psel);
                unsigned vo1 = __byte_perm(w1, 0, psel);
                unsigned long long v0 = *(const unsigned long long*)(Ac + (vo0 ^ u8));
                unsigned long long v1 = *(const unsigned long long*)(Ac + (vo1 ^ u8));
                ADDF2(acc, v0);
                ADDF2(acc, v1);
            }
            if (e + 1 < end) {
                unsigned w0 = *(const unsigned*)(csr + e);
                unsigned vo0 = __byte_perm(w0, 0, psel);
                unsigned long long v0 = *(const unsigned long long*)(Ac + (vo0 ^ u8));
                ADDF2(acc, v0);
                e += 2;
            }
            if (e < end && !half) {
                unsigned long long v = *(const unsigned long long*)(Ac + ((unsigned)csr[e] ^ u8));
                ADDF2(acc, v);
            }
            float ax = __uint_as_float((unsigned)acc);
            float ay = __uint_as_float((unsigned)(acc >> 32));
            ax += __shfl_xor_sync(0xffffffffu, ax, 16);
            ay += __shfl_xor_sync(0xffffffffu, ay, 16);
            if (!half) {
                float dn = dis[n];
                float2 r;
                r.x = tanh_acc(fmaf(ax, dn, bla));
                r.y = tanh_acc(fmaf(ay, dn, blb));
                *(float2*)(Cc + ((unsigned)vn ^ u8)) = r;
            }
        }
    }
    __syncthreads();

    // ================= Layer 3: h2' = (x2 @ W2)*dis, gather -> x3v ==========
    {
        float w2l = W2g[lane];
        float* h2 = (float*)U;
        for (int n = wid; n < NPG; n += 32) {
            float v = *(const float*)(Cc + (swb(n) ^ (lane << 2))) * w2l;
            #pragma unroll
            for (int off = 16; off; off >>= 1) v += __shfl_down_sync(0xffffffffu, v, off);
            if (lane == 0) h2[n] = v * dis[n];   // pre-scaled
        }
    }
    __syncthreads();
    {
        float* h2 = (float*)U;
        float b2 = b2g[0];
        for (int n = wid; n < NPG; n += 32) {
            int beg = indptr[n], end = indptr[n + 1];
            float p = 0.f;
            for (int e = beg + lane; e < end; e += 32)
                p += h2[csr[e] >> 7];            // recover node id from offset
            #pragma unroll
            for (int off = 16; off; off >>= 1) p += __shfl_down_sync(0xffffffffu, p, off);
            if (lane == 0) {
                float tot = p + h2[n];
                x3v[n] = tanh_acc(fmaf(tot, dis[n], b2));
            }
        }
    }
    __syncthreads();

    // ================= stable top-K: bitonic sort of 512 keys ===============
    unsigned long long* keys = (unsigned long long*)U;
    if (tid < 512)
        keys[tid] = ((unsigned long long)ordkey(x3v[tid]) << 32)
                  | (unsigned long long)(0xFFFFFFFFu - (unsigned)tid);
    __syncthreads();
    for (int k = 2; k <= 512; k <<= 1) {
        for (int j = k >> 1; j > 0; j >>= 1) {
            if (tid < 512) {
                int ixj = tid ^ j;
                if (ixj > tid) {
                    unsigned long long a = keys[tid], b = keys[ixj];
                    bool desc = ((tid & k) == 0);
                    if (desc ? (a < b) : (a > b)) { keys[tid] = b; keys[ixj] = a; }
                }
            }
            __syncthreads();
        }
    }

    // ================= tail: conv1 -> maxpool -> conv2 -> lin1 -> lin2 ======
    float* hconv = (float*)Ac;        // 320
    float* hp    = (float*)Ac + 320;  // 160
    float* feat2 = (float*)Ac + 480;  // 192
    float* o1    = (float*)Ac + 672;  // 128
    int*   topn  = (int*)((float*)Ac + 800);  // 20
    float* WS  = (float*)csr;   // CSR dead; 16 KB scratch
    float* c1w = WS;            // 1040
    float* c1b = WS + 1040;     // 16
    float* c2w = WS + 1056;     // 2560
    float* c2b = WS + 3616;     // 32

    for (int i = tid; i < 1040; i += NT) c1w[i] = c1wg[i];
    if (tid < 16) c1b[tid] = c1bg[tid];
    for (int i = tid; i < 2560; i += NT) c2w[i] = c2wg[i];
    if (tid < 32) c2b[tid] = c2bg[tid];
    if (tid < KTOP) topn[tid] = (int)(0xFFFFFFFFu - (unsigned)(keys[tid] & 0xFFFFFFFFull));
    __syncthreads();

    // conv1: [16,K] = relu(pooled . w + b)
    if (tid < 16 * KTOP) {
        int o = tid & 15, k = tid >> 4;
        int n = topn[k];
        int vn = swb(n);
        float acc = c1b[o];
        const float* wrow = c1w + o * 65;
        #pragma unroll
        for (int c = 0; c < 32; c++)
            acc = fmaf(*(const float*)(Bc + (vn ^ (c << 2))), wrow[c], acc);
        #pragma unroll
        for (int c = 0; c < 32; c++)
            acc = fmaf(*(const float*)(Cc + (vn ^ (c << 2))), wrow[32 + c], acc);
        acc = fmaf(x3v[n], wrow[64], acc);
        hconv[o * KTOP + k] = fmaxf(acc, 0.f);
    }
    __syncthreads();

    // maxpool(2,2): [16,20] -> [16,10]
    if (tid < 160) {
        int o = tid / 10, t = tid % 10;
        hp[o * 10 + t] = fmaxf(hconv[o * KTOP + 2 * t], hconv[o * KTOP + 2 * t + 1]);
    }
    __syncthreads();

    // conv2: Conv1d(16,32,5) valid -> [32,6], relu
    if (tid < 192) {
        int o = tid / 6, t = tid % 6;
        float acc = c2b[o];
        #pragma unroll
        for (int i2 = 0; i2 < 16; i2++)
            #pragma unroll
            for (int j = 0; j < 5; j++)
                acc = fmaf(hp[i2 * 10 + t + j], c2w[(o * 16 + i2) * 5 + j], acc);
        feat2[o * 6 + t] = fmaxf(acc, 0.f);
    }
    __syncthreads();

    // lin1: [192] @ [192,128] + b, relu
    if (tid < 128) {
        float acc = l1bg[tid];
        #pragma unroll 8
        for (int c = 0; c < 192; c++)
            acc = fmaf(feat2[c], l1wg[c * 128 + tid], acc);
        o1[tid] = fmaxf(acc, 0.f);
    }
    __syncthreads();

    // lin2: [128] @ [128,2] + b -> out[g,0..1]
    if (tid < 64) {
        int w = tid >> 5, l = tid & 31;
        float p = o1[l]        * l2wg[l * 2 + w]
                + o1[l + 32]   * l2wg[(l + 32) * 2 + w]
                + o1[l + 64]   * l2wg[(l + 64) * 2 + w]
                + o1[l + 96]   * l2wg[(l + 96) * 2 + w];
        #pragma unroll
        for (int off = 16; off; off >>= 1) p += __shfl_down_sync(0xffffffffu, p, off);
        if (l == 0) out[g * 2 + w] = p + l2bg[w];
    }
}

extern "C" void kernel_launch(void* const* d_in, const int* in_sizes, int n_in,
                              void* d_out, int out_size)
{
    const float* x    = (const float*)d_in[0];
    const int*   ei   = (const int*)d_in[1];
    // d_in[2] = batch (unused; graphs are contiguous)
    const float* W0   = (const float*)d_in[3];
    const float* b0   = (const float*)d_in[4];
    const float* W1   = (const float*)d_in[5];
    const float* b1   = (const float*)d_in[6];
    const float* W2   = (const float*)d_in[7];
    const float* b2   = (const float*)d_in[8];
    const float* c1w  = (const float*)d_in[9];
    const float* c1b  = (const float*)d_in[10];
    const float* c2w  = (const float*)d_in[11];
    const float* c2b  = (const float*)d_in[12];
    const float* l1w  = (const float*)d_in[13];
    const float* l1b  = (const float*)d_in[14];
    const float* l2w  = (const float*)d_in[15];
    const float* l2b  = (const float*)d_in[16];
    float* out = (float*)d_out;

    const long E = (long)in_sizes[1] / 2;   // 4,194,304
    const int* esrc = ei;
    const int* edst = ei + E;

    const size_t SMEM = 223248;
    cudaFuncSetAttribute(dgcnn_fused_kernel,
                         cudaFuncAttributeMaxDynamicSharedMemorySize, (int)SMEM);

    dgcnn_fused_kernel<<<NGRAPH, NT, SMEM>>>(
        x, esrc, edst, W0, b0, W1, b1, W2, b2,
        c1w, c1b, c2w, c2b, l1w, l1b, l2w, l2b, out);
}